// round 11
// baseline (speedup 1.0000x reference)
#include <cuda_runtime.h>
#include <cuda_bf16.h>
#include <cstdint>
#include <math.h>

// ---------------- scratch (no allocation allowed) ----------------
__device__ float g_gates[1024 * 4096];     // 16 MB
__device__ float g_atth [1024 * 512];      // 2 MB
__device__ float g_scores[1024 * 64];      // 256 KB
__device__ float g_attout[1024 * 1024];    // 4 MB

// bf16 hi/lo split operands (weights 4096x3072, activations 1024x3072)
__device__ __nv_bfloat16 g_Whi0[4096 * 3072];
__device__ __nv_bfloat16 g_Wlo0[4096 * 3072];
__device__ __nv_bfloat16 g_Whi1[4096 * 3072];
__device__ __nv_bfloat16 g_Wlo1[4096 * 3072];
__device__ __nv_bfloat16 g_Ahi0[1024 * 3072];
__device__ __nv_bfloat16 g_Alo0[1024 * 3072];
__device__ __nv_bfloat16 g_Ahi1[1024 * 3072];
__device__ __nv_bfloat16 g_Alo1[1024 * 3072];

// ================= helpers =================
__device__ __forceinline__ uint32_t smem_u32(const void* p) {
    uint32_t a;
    asm("{ .reg .u64 t; cvta.to.shared.u64 t, %1; cvt.u32.u64 %0, t; }"
        : "=r"(a) : "l"(p));
    return a;
}

#define CP_ASYNC16(dst, src) \
    asm volatile("cp.async.cg.shared.global [%0], [%1], 16;" \
                 :: "r"(dst), "l"(src))
#define CP_COMMIT() asm volatile("cp.async.commit_group;")
#define CP_WAIT2()  asm volatile("cp.async.wait_group 2;")
#define CP_WAIT1()  asm volatile("cp.async.wait_group 1;")
#define CP_WAIT0()  asm volatile("cp.async.wait_group 0;")

#define LDMX4(r0, r1, r2, r3, addr) \
    asm volatile("ldmatrix.sync.aligned.m8n8.x4.shared.b16 {%0,%1,%2,%3}, [%4];" \
                 : "=r"(r0), "=r"(r1), "=r"(r2), "=r"(r3) : "r"(addr))

__device__ __forceinline__ void mma_bf16(float* c, const uint32_t* a,
                                         uint32_t b0, uint32_t b1) {
    asm volatile(
        "mma.sync.aligned.m16n8k16.row.col.f32.bf16.bf16.f32 "
        "{%0,%1,%2,%3}, {%4,%5,%6,%7}, {%8,%9}, {%0,%1,%2,%3};"
        : "+f"(c[0]), "+f"(c[1]), "+f"(c[2]), "+f"(c[3])
        : "r"(a[0]), "r"(a[1]), "r"(a[2]), "r"(a[3]), "r"(b0), "r"(b1));
}

// pack two fp32 -> bf16x2 (lo = k-even, hi = k-odd)
__device__ __forceinline__ uint32_t bf16x2_pack(float lo, float hi) {
    uint32_t d;
    asm("cvt.rn.bf16x2.f32 %0, %1, %2;" : "=r"(d) : "f"(hi), "f"(lo));
    return d;
}

__device__ __forceinline__ void bsplit(float x, __nv_bfloat16& hi, __nv_bfloat16& lo) {
    hi = __float2bfloat16(x);
    lo = __float2bfloat16(x - __bfloat162float(hi));
}

// ================= split (fp32 -> bf16 hi/lo) kernels =================
// weights: dst[n][k] (n<4096, k<3072), k<2048 from Wih (ld 2048), else Whh (ld 1024)
__global__ __launch_bounds__(256) void split_w_kernel(
    const float* __restrict__ Wih, const float* __restrict__ Whh, int which)
{
    __nv_bfloat16* hi = which ? g_Whi1 : g_Whi0;
    __nv_bfloat16* lo = which ? g_Wlo1 : g_Wlo0;
    int q = blockIdx.x * blockDim.x + threadIdx.x;      // float4 index
    if (q >= 4096 * 768) return;
    int row = q / 768, c4 = (q - row * 768) * 4;
    float4 v = (c4 < 2048)
        ? *(const float4*)&Wih[(size_t)row * 2048 + c4]
        : *(const float4*)&Whh[(size_t)row * 1024 + (c4 - 2048)];
    __nv_bfloat16 h[4], l[4];
    bsplit(v.x, h[0], l[0]); bsplit(v.y, h[1], l[1]);
    bsplit(v.z, h[2], l[2]); bsplit(v.w, h[3], l[3]);
    size_t o = (size_t)row * 3072 + c4;
    *(uint2*)&hi[o] = *(uint2*)h;
    *(uint2*)&lo[o] = *(uint2*)l;
}

// activations: src [1024x1024] fp32 (or g_attout) -> A{which} cols [coloff..coloff+1023]
__global__ __launch_bounds__(256) void split_a_kernel(
    const float* __restrict__ src, int use_attout, int which, int coloff)
{
    const float* s = use_attout ? g_attout : src;
    __nv_bfloat16* hi = which ? g_Ahi1 : g_Ahi0;
    __nv_bfloat16* lo = which ? g_Alo1 : g_Alo0;
    int q = blockIdx.x * blockDim.x + threadIdx.x;      // float4 index
    if (q >= 1024 * 256) return;
    int row = q >> 8, c4 = (q & 255) * 4;
    float4 v = *(const float4*)&s[(size_t)row * 1024 + c4];
    __nv_bfloat16 h[4], l[4];
    bsplit(v.x, h[0], l[0]); bsplit(v.y, h[1], l[1]);
    bsplit(v.z, h[2], l[2]); bsplit(v.w, h[3], l[3]);
    size_t o = (size_t)row * 3072 + coloff + c4;
    *(uint2*)&hi[o] = *(uint2*)h;
    *(uint2*)&lo[o] = *(uint2*)l;
}

// ================= tiny init kernels =================
__global__ void init_atth_kernel(const float* __restrict__ b_h2a) {
    int idx = blockIdx.x * blockDim.x + threadIdx.x;
    if (idx < 1024 * 512) g_atth[idx] = b_h2a[idx & 511];
}
__global__ void init_scores_kernel(const float* __restrict__ b_alpha) {
    int idx = blockIdx.x * blockDim.x + threadIdx.x;
    if (idx < 1024 * 64) g_scores[idx] = b_alpha[0];
}

// ======================================================================
// bf16 gates GEMM (3-term via augmented K'=9216) — unchanged (validated R10):
//   gates = A'[1024,9216] @ W'[4096,9216]^T + b_ih + b_hh -> g_gates
// ======================================================================
__global__ void __launch_bounds__(512) bf16_gates_kernel(
    int which, const float* __restrict__ e0, const float* __restrict__ e1)
{
    constexpr int ASZ = 128 * 128;          // bytes per A stage (16384)
    constexpr int BSZ = 256 * 128;          // bytes per B stage (32768)
    constexpr int STG = ASZ + BSZ;          // 49152
    constexpr int T = 144;                  // 9216 / 64

    const __nv_bfloat16* Ahi = which ? g_Ahi1 : g_Ahi0;
    const __nv_bfloat16* Alo = which ? g_Alo1 : g_Alo0;
    const __nv_bfloat16* Whi = which ? g_Whi1 : g_Whi0;
    const __nv_bfloat16* Wlo = which ? g_Wlo1 : g_Wlo0;

    extern __shared__ char smc[];
    const uint32_t smu = smem_u32(smc);

    const int tid = threadIdx.x;
    const int lane = tid & 31, w = tid >> 5;
    const int wm = w & 3, wn = w >> 2;
    const int g = lane >> 2, tig = lane & 3;
    const int sub = lane >> 3, sr = lane & 7;
    const int m0 = blockIdx.y * 128, n0 = blockIdx.x * 256;

    float acc[2][8][4];
#pragma unroll
    for (int mt = 0; mt < 2; mt++)
#pragma unroll
        for (int nt = 0; nt < 8; nt++)
#pragma unroll
            for (int r = 0; r < 4; r++) acc[mt][nt][r] = 0.f;

    auto prefetch = [&](int t, int buf) {
        const int seg = t / 48;
        const int kk = t * 64 - seg * 3072;
        const __nv_bfloat16* As = (seg == 1) ? Alo : Ahi;
        const __nv_bfloat16* Bs = (seg == 2) ? Wlo : Whi;
        const uint32_t abase = smu + (uint32_t)buf * STG;
        const uint32_t bbase = abase + ASZ;
#pragma unroll
        for (int i = 0; i < 2; i++) {                 // A: 1024 chunks / 512 thr
            int q = tid + i * 512;
            int row = q >> 3, c = q & 7;
            CP_ASYNC16(abase + row * 128 + ((c ^ (row & 7)) << 4),
                       (const void*)&As[(size_t)(m0 + row) * 3072 + kk + c * 8]);
        }
#pragma unroll
        for (int i = 0; i < 4; i++) {                 // B: 2048 chunks / 512 thr
            int q = tid + i * 512;
            int row = q >> 3, c = q & 7;
            CP_ASYNC16(bbase + row * 128 + ((c ^ (row & 7)) << 4),
                       (const void*)&Bs[(size_t)(n0 + row) * 3072 + kk + c * 8]);
        }
        CP_COMMIT();
    };

    prefetch(0, 0);
    prefetch(1, 1);

    for (int t = 0; t < T; t++) {
        const int buf = t % 3;
        if (t + 2 < T) { prefetch(t + 2, (t + 2) % 3); CP_WAIT2(); }
        else if (t + 1 < T) { CP_WAIT1(); }
        else { CP_WAIT0(); }
        __syncthreads();

        const uint32_t abase = smu + (uint32_t)buf * STG;
        const uint32_t bbase = abase + ASZ;

#pragma unroll
        for (int s = 0; s < 4; s++) {
            uint32_t a[2][4];
#pragma unroll
            for (int mt = 0; mt < 2; mt++) {
                int r = wm * 32 + mt * 16 + (sub & 1) * 8 + sr;
                int ch = 2 * s + (sub >> 1);
                LDMX4(a[mt][0], a[mt][1], a[mt][2], a[mt][3],
                      abase + r * 128 + ((ch ^ (r & 7)) << 4));
            }
#pragma unroll
            for (int ntp = 0; ntp < 4; ntp++) {
                int r = wn * 64 + ntp * 16 + ((sub >> 1) & 1) * 8 + sr;
                int ch = 2 * s + (sub & 1);
                uint32_t b0, b1, b2, b3;
                LDMX4(b0, b1, b2, b3, bbase + r * 128 + ((ch ^ (r & 7)) << 4));
                mma_bf16(acc[0][2 * ntp],     a[0], b0, b1);
                mma_bf16(acc[1][2 * ntp],     a[1], b0, b1);
                mma_bf16(acc[0][2 * ntp + 1], a[0], b2, b3);
                mma_bf16(acc[1][2 * ntp + 1], a[1], b2, b3);
            }
        }
        __syncthreads();
    }

    // epilogue: gates + biases -> g_gates (device symbol)
#pragma unroll
    for (int mt = 0; mt < 2; mt++) {
        const int r0 = m0 + wm * 32 + mt * 16 + g;
        const int r1 = r0 + 8;
#pragma unroll
        for (int nt = 0; nt < 8; nt++) {
            const int cb = n0 + wn * 64 + nt * 8 + tig * 2;
            float2 bA = *(const float2*)&e0[cb];
            float2 bB = *(const float2*)&e1[cb];
            const float* a = acc[mt][nt];
            float2 v0 = { a[0] + bA.x + bB.x, a[1] + bA.y + bB.y };
            float2 v1 = { a[2] + bA.x + bB.x, a[3] + bA.y + bB.y };
            *(float2*)&g_gates[(size_t)r0 * 4096 + cb] = v0;
            *(float2*)&g_gates[(size_t)r1 * 4096 + cb] = v1;
        }
    }
}

// ======================================================================
// bf16 scores GEMM (was tf32): in-register fp32->bf16x2 pack, m16n8k16.
// scores[b,s] += sum_n Walpha[n]*tanh(clip@Wctx^T + bctx + atth[b]) (atomic)
// M=65536, N=512, K=1024; BM=128, BN=256, BK=32. Layout/pipeline unchanged.
// Fragment maps (match validated gates kernel):
//   a0={A[g][2t,2t+1]}, a1=row+8, a2=k+8, a3=row+8&k+8; b0={B[g][2t,2t+1]}, b1=k+8.
// ======================================================================
__global__ void __launch_bounds__(512) mma_scores_kernel(
    const float* __restrict__ A0,
    const float* __restrict__ B01,
    const float* __restrict__ e0, const float* __restrict__ e1)
{
    constexpr int PITCH = 36;
    constexpr int AF = 128 * PITCH;
    constexpr int BF = 256 * PITCH;
    constexpr int STGF = AF + BF;

    extern __shared__ float smf[];
    const uint32_t smu = smem_u32(smf);

    const int tid = threadIdx.x;
    const int lane = tid & 31, w = tid >> 5;
    const int wm = w & 3, wn = w >> 2;
    const int g = lane >> 2, tig = lane & 3;
    const int m0 = blockIdx.y * 128, n0 = blockIdx.x * 256;

    float acc[2][8][4];
#pragma unroll
    for (int mt = 0; mt < 2; mt++)
#pragma unroll
        for (int nt = 0; nt < 8; nt++)
#pragma unroll
            for (int r = 0; r < 4; r++) acc[mt][nt][r] = 0.f;

    auto prefetch = [&](int t, int buf) {
        const int k0 = t * 32;
        const uint32_t abase = smu + (uint32_t)buf * STGF * 4;
        const uint32_t bbase = abase + AF * 4;
#pragma unroll
        for (int i = 0; i < 2; i++) {
            int q = tid + i * 512;
            int row = q >> 3, c4 = q & 7;
            CP_ASYNC16(abase + (uint32_t)(row * PITCH + c4 * 4) * 4,
                       (const void*)&A0[(size_t)(m0 + row) * 1024 + k0 + c4 * 4]);
        }
#pragma unroll
        for (int i = 0; i < 4; i++) {
            int q = tid + i * 512;
            int row = q >> 3, c4 = q & 7;
            CP_ASYNC16(bbase + (uint32_t)(row * PITCH + c4 * 4) * 4,
                       (const void*)&B01[(size_t)(n0 + row) * 1024 + k0 + c4 * 4]);
        }
        CP_COMMIT();
    };

    prefetch(0, 0);

    for (int t = 0; t < 32; t++) {
        const int buf = t & 1;
        if (t + 1 < 32) { prefetch(t + 1, buf ^ 1); CP_WAIT1(); }
        else            { CP_WAIT0(); }
        __syncthreads();

        const float* As = smf + buf * STGF;
        const float* Bs = As + AF;

#pragma unroll
        for (int s2 = 0; s2 < 2; s2++) {           // two k16 steps per BK=32
            const int k16 = s2 * 16;
            uint32_t a[2][4];
#pragma unroll
            for (int mt = 0; mt < 2; mt++) {
                const float* ap = As + (wm * 32 + mt * 16 + g) * PITCH + k16 + 2 * tig;
                float2 v0 = *(const float2*)&ap[0];            // rows g,   k 2t
                float2 v1 = *(const float2*)&ap[8 * PITCH];    // rows g+8, k 2t
                float2 v2 = *(const float2*)&ap[8];            // rows g,   k 2t+8
                float2 v3 = *(const float2*)&ap[8 * PITCH + 8];
                a[mt][0] = bf16x2_pack(v0.x, v0.y);
                a[mt][1] = bf16x2_pack(v1.x, v1.y);
                a[mt][2] = bf16x2_pack(v2.x, v2.y);
                a[mt][3] = bf16x2_pack(v3.x, v3.y);
            }
#pragma unroll
            for (int nt = 0; nt < 8; nt++) {
                const float* bp = Bs + (wn * 64 + nt * 8 + g) * PITCH + k16 + 2 * tig;
                float2 u0 = *(const float2*)&bp[0];            // n g, k 2t
                float2 u1 = *(const float2*)&bp[8];            // n g, k 2t+8
                uint32_t b0 = bf16x2_pack(u0.x, u0.y);
                uint32_t b1 = bf16x2_pack(u1.x, u1.y);
#pragma unroll
                for (int mt = 0; mt < 2; mt++) mma_bf16(acc[mt][nt], a[mt], b0, b1);
            }
        }
        __syncthreads();
    }

#pragma unroll
    for (int mt = 0; mt < 2; mt++) {
        const int r0 = m0 + wm * 32 + mt * 16 + g;
        const int r1 = r0 + 8;
        const int bb0 = r0 >> 6, bb1 = r1 >> 6;
        float s0 = 0.f, s1 = 0.f;
#pragma unroll
        for (int nt = 0; nt < 8; nt++) {
            const int cb = n0 + wn * 64 + nt * 8 + tig * 2;
            float2 bc = *(const float2*)&e0[cb];
            float2 wa = *(const float2*)&e1[cb];
            float2 a0 = *(const float2*)&g_atth[(size_t)bb0 * 512 + cb];
            float2 a1 = *(const float2*)&g_atth[(size_t)bb1 * 512 + cb];
            const float* a = acc[mt][nt];
            s0 += tanhf(a[0] + bc.x + a0.x) * wa.x + tanhf(a[1] + bc.y + a0.y) * wa.y;
            s1 += tanhf(a[2] + bc.x + a1.x) * wa.x + tanhf(a[3] + bc.y + a1.y) * wa.y;
        }
        s0 += __shfl_xor_sync(0xffffffffu, s0, 1);
        s0 += __shfl_xor_sync(0xffffffffu, s0, 2);
        s1 += __shfl_xor_sync(0xffffffffu, s1, 1);
        s1 += __shfl_xor_sync(0xffffffffu, s1, 2);
        if (tig == 0) {
            atomicAdd(&g_scores[r0], s0);
            atomicAdd(&g_scores[r1], s1);
        }
    }
}

// ======================================================================
// GEMM (small, SIMT): att_h += pre_h1 @ W_h2a^T  (split-K=4)
// ======================================================================
__global__ __launch_bounds__(256) void gemm_atth_kernel(
    const float* __restrict__ h1, const float* __restrict__ Wh2a)
{
    __shared__ __align__(16) float As[16][132];
    __shared__ __align__(16) float Ws[16][132];
    const int tid = threadIdx.x;
    const int tx = tid & 15, ty = tid >> 4;
    const int m0 = blockIdx.y * 128, n0 = blockIdx.x * 128;
    const int kbeg = blockIdx.z * 256, kend = kbeg + 256;

    float acc[8][8];
#pragma unroll
    for (int i = 0; i < 8; i++)
#pragma unroll
        for (int j = 0; j < 8; j++) acc[i][j] = 0.f;

    for (int k0 = kbeg; k0 < kend; k0 += 16) {
#pragma unroll
        for (int i = 0; i < 2; i++) {
            int lin = tid + i * 256;
            int row = lin >> 2, k4 = (lin & 3) << 2;
            float4 va = *(const float4*)&h1[(size_t)(m0 + row) * 1024 + k0 + k4];
            As[k4 + 0][row] = va.x; As[k4 + 1][row] = va.y;
            As[k4 + 2][row] = va.z; As[k4 + 3][row] = va.w;
            float4 vw = *(const float4*)&Wh2a[(size_t)(n0 + row) * 1024 + k0 + k4];
            Ws[k4 + 0][row] = vw.x; Ws[k4 + 1][row] = vw.y;
            Ws[k4 + 2][row] = vw.z; Ws[k4 + 3][row] = vw.w;
        }
        __syncthreads();
#pragma unroll
        for (int kk = 0; kk < 16; kk++) {
            float4 a0 = *(const float4*)&As[kk][4 * ty];
            float4 a1 = *(const float4*)&As[kk][64 + 4 * ty];
            float4 b0 = *(const float4*)&Ws[kk][4 * tx];
            float4 b1 = *(const float4*)&Ws[kk][64 + 4 * tx];
            float a[8] = {a0.x, a0.y, a0.z, a0.w, a1.x, a1.y, a1.z, a1.w};
            float b[8] = {b0.x, b0.y, b0.z, b0.w, b1.x, b1.y, b1.z, b1.w};
#pragma unroll
            for (int i = 0; i < 8; i++)
#pragma unroll
                for (int j = 0; j < 8; j++)
                    acc[i][j] = fmaf(a[i], b[j], acc[i][j]);
        }
        __syncthreads();
    }
#pragma unroll
    for (int i = 0; i < 8; i++) {
        int r = (i < 4) ? (4 * ty + i) : (64 + 4 * ty + i - 4);
#pragma unroll
        for (int j = 0; j < 8; j++) {
            int c = (j < 4) ? (4 * tx + j) : (64 + 4 * tx + j - 4);
            atomicAdd(&g_atth[(size_t)(m0 + r) * 512 + n0 + c], acc[i][j]);
        }
    }
}

// ======================================================================
// softmax over S=64 (mask + renorm) + weighted sum of clip -> g_attout
// ======================================================================
__global__ __launch_bounds__(256) void softmax_attout_kernel(
    const float* __restrict__ clip, const int* __restrict__ mask)
{
    const int b = blockIdx.x;
    const int tid = threadIdx.x;
    __shared__ float w[64];
    __shared__ float stat;

    if (tid < 64) w[tid] = g_scores[b * 64 + tid];
    __syncthreads();
    if (tid == 0) {
        float m = w[0];
        for (int s = 1; s < 64; s++) m = fmaxf(m, w[s]);
        stat = m;
    }
    __syncthreads();
    if (tid < 64) w[tid] = expf(w[tid] - stat);
    __syncthreads();
    if (tid == 0) {
        float s = 0.f;
        for (int i = 0; i < 64; i++) s += w[i];
        stat = s;
    }
    __syncthreads();
    if (tid < 64) w[tid] = (w[tid] / stat) * (float)mask[b * 64 + tid];
    __syncthreads();
    if (tid == 0) {
        float s = 0.f;
        for (int i = 0; i < 64; i++) s += w[i];
        stat = s;
    }
    __syncthreads();
    if (tid < 64) w[tid] = w[tid] / stat;
    __syncthreads();

    for (int d = tid; d < 1024; d += 256) {
        float acc = 0.f;
#pragma unroll 8
        for (int s = 0; s < 64; s++)
            acc += w[s] * clip[((size_t)b * 64 + s) * 1024 + d];
        g_attout[(size_t)b * 1024 + d] = acc;
    }
}

// ======================================================================
// LSTM pointwise
// ======================================================================
__global__ __launch_bounds__(256) void lstm_pointwise_kernel(
    const float* __restrict__ state_c, int stream, float* __restrict__ out)
{
    int idx = blockIdx.x * blockDim.x + threadIdx.x;
    int b = idx >> 10, j = idx & 1023;
    const float* g = g_gates + (size_t)b * 4096;
    float ig = 1.f / (1.f + expf(-g[j]));
    float fg = 1.f / (1.f + expf(-g[1024 + j]));
    float gg = tanhf(g[2048 + j]);
    float og = 1.f / (1.f + expf(-g[3072 + j]));
    float c_old = state_c[(size_t)stream * 1048576 + idx];
    float c_new = fg * c_old + ig * gg;
    float h_new = og * tanhf(c_new);
    out[(size_t)b * 2048 + stream * 1024 + j] = h_new;
    out[2097152 + (size_t)stream * 1048576 + idx] = h_new;
    out[4194304 + (size_t)stream * 1048576 + idx] = c_new;
}

// ======================================================================
extern "C" void kernel_launch(void* const* d_in, const int* in_sizes, int n_in,
                              void* d_out, int out_size)
{
    const float* xt       = (const float*)d_in[0];
    const float* event    = (const float*)d_in[2];
    const float* clip     = (const float*)d_in[3];
    const int*   clipmask = (const int*)  d_in[4];
    const float* state_h  = (const float*)d_in[5];
    const float* state_c  = (const float*)d_in[6];
    const float* W_ih0    = (const float*)d_in[7];
    const float* b_ih0    = (const float*)d_in[8];
    const float* W_hh0    = (const float*)d_in[9];
    const float* b_hh0    = (const float*)d_in[10];
    const float* W_ih1    = (const float*)d_in[11];
    const float* b_ih1    = (const float*)d_in[12];
    const float* W_hh1    = (const float*)d_in[13];
    const float* b_hh1    = (const float*)d_in[14];
    const float* W_ctx    = (const float*)d_in[15];
    const float* b_ctx    = (const float*)d_in[16];
    const float* W_h2a    = (const float*)d_in[17];
    const float* b_h2a    = (const float*)d_in[18];
    const float* W_alpha  = (const float*)d_in[19];
    const float* b_alpha  = (const float*)d_in[20];
    float* out = (float*)d_out;

    const float* h0 = state_h;
    const float* h1 = state_h + 1048576;

    const int SMEM_G = 3 * 49152;   // 147456 B (bf16 gates, 3 stages)
    const int SMEM_S = 2 * 55296;   // 110592 B (scores, 2 stages)
    cudaFuncSetAttribute(bf16_gates_kernel,
                         cudaFuncAttributeMaxDynamicSharedMemorySize, SMEM_G);
    cudaFuncSetAttribute(mma_scores_kernel,
                         cudaFuncAttributeMaxDynamicSharedMemorySize, SMEM_S);

    // ---- operand conversions (hi/lo bf16 splits) ----
    split_w_kernel<<<(4096 * 768 + 255) / 256, 256>>>(W_ih0, W_hh0, 0);
    split_w_kernel<<<(4096 * 768 + 255) / 256, 256>>>(W_ih1, W_hh1, 1);
    split_a_kernel<<<1024, 256>>>(xt,    0, 0, 0);
    split_a_kernel<<<1024, 256>>>(event, 0, 0, 1024);
    split_a_kernel<<<1024, 256>>>(h0,    0, 0, 2048);
    split_a_kernel<<<1024, 256>>>(xt,    0, 1, 0);
    split_a_kernel<<<1024, 256>>>(h1,    0, 1, 2048);

    // ---- attention pre-work ----
    init_atth_kernel<<<2048, 256>>>(b_h2a);
    init_scores_kernel<<<256, 256>>>(b_alpha);
    gemm_atth_kernel<<<dim3(4, 8, 4), 256>>>(h1, W_h2a);

    // ---- stream 0 LSTM ----
    bf16_gates_kernel<<<dim3(16, 8), 512, SMEM_G>>>(0, b_ih0, b_hh0);
    lstm_pointwise_kernel<<<4096, 256>>>(state_c, 0, out);

    // ---- attention scores + softmax + context ----
    mma_scores_kernel<<<dim3(2, 512), 512, SMEM_S>>>(clip, W_ctx, b_ctx, W_alpha);
    softmax_attout_kernel<<<1024, 256>>>(clip, clipmask);
    split_a_kernel<<<1024, 256>>>(nullptr, 1, 1, 1024);   // att -> A1 cols 1024..2047

    // ---- stream 1 LSTM ----
    bf16_gates_kernel<<<dim3(16, 8), 512, SMEM_G>>>(1, b_ih1, b_hh1);
    lstm_pointwise_kernel<<<4096, 256>>>(state_c, 1, out);
}

// round 12
// speedup vs baseline: 1.4863x; 1.4863x over previous
#include <cuda_runtime.h>
#include <cuda_fp16.h>
#include <cstdint>
#include <math.h>

// ---------------- scratch (no allocation allowed) ----------------
__device__ float g_gates[1024 * 4096];     // 16 MB
__device__ float g_atth [1024 * 512];      // 2 MB
__device__ float g_scores[1024 * 64];      // 256 KB
__device__ float g_attout[1024 * 1024];    // 4 MB

// fp16 operands (weights 4096x3072, activations 1024x3072)
__device__ __half g_W0[4096 * 3072];
__device__ __half g_W1[4096 * 3072];
__device__ __half g_A0[1024 * 3072];
__device__ __half g_A1[1024 * 3072];

// ================= helpers =================
__device__ __forceinline__ uint32_t smem_u32(const void* p) {
    uint32_t a;
    asm("{ .reg .u64 t; cvta.to.shared.u64 t, %1; cvt.u32.u64 %0, t; }"
        : "=r"(a) : "l"(p));
    return a;
}

#define CP_ASYNC16(dst, src) \
    asm volatile("cp.async.cg.shared.global [%0], [%1], 16;" \
                 :: "r"(dst), "l"(src))
#define CP_COMMIT() asm volatile("cp.async.commit_group;")
#define CP_WAIT2()  asm volatile("cp.async.wait_group 2;")
#define CP_WAIT1()  asm volatile("cp.async.wait_group 1;")
#define CP_WAIT0()  asm volatile("cp.async.wait_group 0;")

#define LDMX4(r0, r1, r2, r3, addr) \
    asm volatile("ldmatrix.sync.aligned.m8n8.x4.shared.b16 {%0,%1,%2,%3}, [%4];" \
                 : "=r"(r0), "=r"(r1), "=r"(r2), "=r"(r3) : "r"(addr))

__device__ __forceinline__ void mma_f16(float* c, const uint32_t* a,
                                        uint32_t b0, uint32_t b1) {
    asm volatile(
        "mma.sync.aligned.m16n8k16.row.col.f32.f16.f16.f32 "
        "{%0,%1,%2,%3}, {%4,%5,%6,%7}, {%8,%9}, {%0,%1,%2,%3};"
        : "+f"(c[0]), "+f"(c[1]), "+f"(c[2]), "+f"(c[3])
        : "r"(a[0]), "r"(a[1]), "r"(a[2]), "r"(a[3]), "r"(b0), "r"(b1));
}

__device__ __forceinline__ void mma8(float* c, const uint32_t* a, const uint32_t* b) {
    asm volatile(
        "mma.sync.aligned.m16n8k8.row.col.f32.tf32.tf32.f32 "
        "{%0,%1,%2,%3}, {%4,%5,%6,%7}, {%8,%9}, {%0,%1,%2,%3};"
        : "+f"(c[0]), "+f"(c[1]), "+f"(c[2]), "+f"(c[3])
        : "r"(a[0]), "r"(a[1]), "r"(a[2]), "r"(a[3]), "r"(b[0]), "r"(b[1]));
}

__device__ __forceinline__ uint32_t tf32_rna(float x) {
    uint32_t u;
    asm("cvt.rna.tf32.f32 %0, %1;" : "=r"(u) : "f"(x));
    return u;
}

// ================= convert (fp32 -> fp16) kernels =================
// weights: dst[n][k] (n<4096, k<3072), k<2048 from Wih (ld 2048), else Whh (ld 1024)
__global__ __launch_bounds__(256) void conv_w_kernel(
    const float* __restrict__ Wih, const float* __restrict__ Whh, int which)
{
    __half* dst = which ? g_W1 : g_W0;
    int q = blockIdx.x * blockDim.x + threadIdx.x;      // float4 index
    if (q >= 4096 * 768) return;
    int row = q / 768, c4 = (q - row * 768) * 4;
    float4 v = (c4 < 2048)
        ? *(const float4*)&Wih[(size_t)row * 2048 + c4]
        : *(const float4*)&Whh[(size_t)row * 1024 + (c4 - 2048)];
    __half h[4] = { __float2half(v.x), __float2half(v.y),
                    __float2half(v.z), __float2half(v.w) };
    *(uint2*)&dst[(size_t)row * 3072 + c4] = *(uint2*)h;
}

// activations: src [1024x1024] fp32 (or g_attout) -> A{which} cols [coloff..]
__global__ __launch_bounds__(256) void conv_a_kernel(
    const float* __restrict__ src, int use_attout, int which, int coloff)
{
    const float* s = use_attout ? g_attout : src;
    __half* dst = which ? g_A1 : g_A0;
    int q = blockIdx.x * blockDim.x + threadIdx.x;      // float4 index
    if (q >= 1024 * 256) return;
    int row = q >> 8, c4 = (q & 255) * 4;
    float4 v = *(const float4*)&s[(size_t)row * 1024 + c4];
    __half h[4] = { __float2half(v.x), __float2half(v.y),
                    __float2half(v.z), __float2half(v.w) };
    *(uint2*)&dst[(size_t)row * 3072 + coloff + c4] = *(uint2*)h;
}

// ================= tiny init kernels =================
__global__ void init_atth_kernel(const float* __restrict__ b_h2a) {
    int idx = blockIdx.x * blockDim.x + threadIdx.x;
    if (idx < 1024 * 512) g_atth[idx] = b_h2a[idx & 511];
}
__global__ void init_scores_kernel(const float* __restrict__ b_alpha) {
    int idx = blockIdx.x * blockDim.x + threadIdx.x;
    if (idx < 1024 * 64) g_scores[idx] = b_alpha[0];
}

// ======================================================================
// fp16 gates GEMM (1-pass, K=3072):
//   gates = A[1024,3072] @ W[4096,3072]^T + b_ih + b_hh -> g_gates
// BM=128, BN=256, BK=64 fp16 (128B rows, XOR swizzle), 3-stage cp.async,
// 512 threads (16 warps 4m x 4n), warp tile 32x64, ldmatrix + m16n8k16.
// Structure identical to the R10-validated bf16 gates kernel (b16-agnostic).
// ======================================================================
__global__ void __launch_bounds__(512) fp16_gates_kernel(
    int which, const float* __restrict__ e0, const float* __restrict__ e1)
{
    constexpr int ASZ = 128 * 128;          // bytes per A stage (16384)
    constexpr int BSZ = 256 * 128;          // bytes per B stage (32768)
    constexpr int STG = ASZ + BSZ;          // 49152
    constexpr int T = 48;                   // 3072 / 64

    const __half* Ah = which ? g_A1 : g_A0;
    const __half* Wh = which ? g_W1 : g_W0;

    extern __shared__ char smc[];
    const uint32_t smu = smem_u32(smc);

    const int tid = threadIdx.x;
    const int lane = tid & 31, w = tid >> 5;
    const int wm = w & 3, wn = w >> 2;
    const int g = lane >> 2, tig = lane & 3;
    const int sub = lane >> 3, sr = lane & 7;
    const int m0 = blockIdx.y * 128, n0 = blockIdx.x * 256;

    float acc[2][8][4];
#pragma unroll
    for (int mt = 0; mt < 2; mt++)
#pragma unroll
        for (int nt = 0; nt < 8; nt++)
#pragma unroll
            for (int r = 0; r < 4; r++) acc[mt][nt][r] = 0.f;

    auto prefetch = [&](int t, int buf) {
        const int kk = t * 64;
        const uint32_t abase = smu + (uint32_t)buf * STG;
        const uint32_t bbase = abase + ASZ;
#pragma unroll
        for (int i = 0; i < 2; i++) {                 // A: 1024 chunks / 512 thr
            int q = tid + i * 512;
            int row = q >> 3, c = q & 7;
            CP_ASYNC16(abase + row * 128 + ((c ^ (row & 7)) << 4),
                       (const void*)&Ah[(size_t)(m0 + row) * 3072 + kk + c * 8]);
        }
#pragma unroll
        for (int i = 0; i < 4; i++) {                 // B: 2048 chunks / 512 thr
            int q = tid + i * 512;
            int row = q >> 3, c = q & 7;
            CP_ASYNC16(bbase + row * 128 + ((c ^ (row & 7)) << 4),
                       (const void*)&Wh[(size_t)(n0 + row) * 3072 + kk + c * 8]);
        }
        CP_COMMIT();
    };

    prefetch(0, 0);
    prefetch(1, 1);

    for (int t = 0; t < T; t++) {
        const int buf = t % 3;
        if (t + 2 < T) { prefetch(t + 2, (t + 2) % 3); CP_WAIT2(); }
        else if (t + 1 < T) { CP_WAIT1(); }
        else { CP_WAIT0(); }
        __syncthreads();

        const uint32_t abase = smu + (uint32_t)buf * STG;
        const uint32_t bbase = abase + ASZ;

#pragma unroll
        for (int s = 0; s < 4; s++) {
            uint32_t a[2][4];
#pragma unroll
            for (int mt = 0; mt < 2; mt++) {
                int r = wm * 32 + mt * 16 + (sub & 1) * 8 + sr;
                int ch = 2 * s + (sub >> 1);
                LDMX4(a[mt][0], a[mt][1], a[mt][2], a[mt][3],
                      abase + r * 128 + ((ch ^ (r & 7)) << 4));
            }
#pragma unroll
            for (int ntp = 0; ntp < 4; ntp++) {
                int r = wn * 64 + ntp * 16 + ((sub >> 1) & 1) * 8 + sr;
                int ch = 2 * s + (sub & 1);
                uint32_t b0, b1, b2, b3;
                LDMX4(b0, b1, b2, b3, bbase + r * 128 + ((ch ^ (r & 7)) << 4));
                mma_f16(acc[0][2 * ntp],     a[0], b0, b1);
                mma_f16(acc[1][2 * ntp],     a[1], b0, b1);
                mma_f16(acc[0][2 * ntp + 1], a[0], b2, b3);
                mma_f16(acc[1][2 * ntp + 1], a[1], b2, b3);
            }
        }
        __syncthreads();
    }

    // epilogue: gates + biases -> g_gates (device symbol)
#pragma unroll
    for (int mt = 0; mt < 2; mt++) {
        const int r0 = m0 + wm * 32 + mt * 16 + g;
        const int r1 = r0 + 8;
#pragma unroll
        for (int nt = 0; nt < 8; nt++) {
            const int cb = n0 + wn * 64 + nt * 8 + tig * 2;
            float2 bA = *(const float2*)&e0[cb];
            float2 bB = *(const float2*)&e1[cb];
            const float* a = acc[mt][nt];
            float2 v0 = { a[0] + bA.x + bB.x, a[1] + bA.y + bB.y };
            float2 v1 = { a[2] + bA.x + bB.x, a[3] + bA.y + bB.y };
            *(float2*)&g_gates[(size_t)r0 * 4096 + cb] = v0;
            *(float2*)&g_gates[(size_t)r1 * 4096 + cb] = v1;
        }
    }
}

// ======================================================================
// tf32 mma.sync scores GEMM (exact R10-validated version):
// scores[b,s] += sum_n Walpha[n]*tanh(clip@Wctx^T + bctx + atth[b]) (atomic)
// M=65536, N=512, K=1024; BM=128, BN=256, BK=32.
// ======================================================================
__global__ void __launch_bounds__(512) mma_scores_kernel(
    const float* __restrict__ A0,
    const float* __restrict__ B01,
    const float* __restrict__ e0, const float* __restrict__ e1)
{
    constexpr int PITCH = 36;
    constexpr int AF = 128 * PITCH;
    constexpr int BF = 256 * PITCH;
    constexpr int STGF = AF + BF;

    extern __shared__ float smf[];
    const uint32_t smu = smem_u32(smf);

    const int tid = threadIdx.x;
    const int lane = tid & 31, w = tid >> 5;
    const int wm = w & 3, wn = w >> 2;
    const int g = lane >> 2, tig = lane & 3;
    const int m0 = blockIdx.y * 128, n0 = blockIdx.x * 256;

    float acc[2][8][4];
#pragma unroll
    for (int mt = 0; mt < 2; mt++)
#pragma unroll
        for (int nt = 0; nt < 8; nt++)
#pragma unroll
            for (int r = 0; r < 4; r++) acc[mt][nt][r] = 0.f;

    auto prefetch = [&](int t, int buf) {
        const int k0 = t * 32;
        const uint32_t abase = smu + (uint32_t)buf * STGF * 4;
        const uint32_t bbase = abase + AF * 4;
#pragma unroll
        for (int i = 0; i < 2; i++) {
            int q = tid + i * 512;
            int row = q >> 3, c4 = q & 7;
            CP_ASYNC16(abase + (uint32_t)(row * PITCH + c4 * 4) * 4,
                       (const void*)&A0[(size_t)(m0 + row) * 1024 + k0 + c4 * 4]);
        }
#pragma unroll
        for (int i = 0; i < 4; i++) {
            int q = tid + i * 512;
            int row = q >> 3, c4 = q & 7;
            CP_ASYNC16(bbase + (uint32_t)(row * PITCH + c4 * 4) * 4,
                       (const void*)&B01[(size_t)(n0 + row) * 1024 + k0 + c4 * 4]);
        }
        CP_COMMIT();
    };

    prefetch(0, 0);

    for (int t = 0; t < 32; t++) {
        const int buf = t & 1;
        if (t + 1 < 32) { prefetch(t + 1, buf ^ 1); CP_WAIT1(); }
        else            { CP_WAIT0(); }
        __syncthreads();

        const float* As = smf + buf * STGF;
        const float* Bs = As + AF;

#pragma unroll
        for (int s = 0; s < 4; s++) {
            uint32_t ah[2][4];
#pragma unroll
            for (int mt = 0; mt < 2; mt++) {
                const float* ap = As + (wm * 32 + mt * 16 + g) * PITCH + s * 8 + tig;
                ah[mt][0] = tf32_rna(ap[0]);
                ah[mt][1] = tf32_rna(ap[8 * PITCH]);
                ah[mt][2] = tf32_rna(ap[4]);
                ah[mt][3] = tf32_rna(ap[8 * PITCH + 4]);
            }
#pragma unroll
            for (int nt = 0; nt < 8; nt++) {
                const float* bp = Bs + (wn * 64 + nt * 8 + g) * PITCH + s * 8 + tig;
                uint32_t bh[2] = { tf32_rna(bp[0]), tf32_rna(bp[4]) };
#pragma unroll
                for (int mt = 0; mt < 2; mt++) mma8(acc[mt][nt], ah[mt], bh);
            }
        }
        __syncthreads();
    }

#pragma unroll
    for (int mt = 0; mt < 2; mt++) {
        const int r0 = m0 + wm * 32 + mt * 16 + g;
        const int r1 = r0 + 8;
        const int bb0 = r0 >> 6, bb1 = r1 >> 6;
        float s0 = 0.f, s1 = 0.f;
#pragma unroll
        for (int nt = 0; nt < 8; nt++) {
            const int cb = n0 + wn * 64 + nt * 8 + tig * 2;
            float2 bc = *(const float2*)&e0[cb];
            float2 wa = *(const float2*)&e1[cb];
            float2 a0 = *(const float2*)&g_atth[(size_t)bb0 * 512 + cb];
            float2 a1 = *(const float2*)&g_atth[(size_t)bb1 * 512 + cb];
            const float* a = acc[mt][nt];
            s0 += tanhf(a[0] + bc.x + a0.x) * wa.x + tanhf(a[1] + bc.y + a0.y) * wa.y;
            s1 += tanhf(a[2] + bc.x + a1.x) * wa.x + tanhf(a[3] + bc.y + a1.y) * wa.y;
        }
        s0 += __shfl_xor_sync(0xffffffffu, s0, 1);
        s0 += __shfl_xor_sync(0xffffffffu, s0, 2);
        s1 += __shfl_xor_sync(0xffffffffu, s1, 1);
        s1 += __shfl_xor_sync(0xffffffffu, s1, 2);
        if (tig == 0) {
            atomicAdd(&g_scores[r0], s0);
            atomicAdd(&g_scores[r1], s1);
        }
    }
}

// ======================================================================
// GEMM (small, SIMT): att_h += pre_h1 @ W_h2a^T  (split-K=4)
// ======================================================================
__global__ __launch_bounds__(256) void gemm_atth_kernel(
    const float* __restrict__ h1, const float* __restrict__ Wh2a)
{
    __shared__ __align__(16) float As[16][132];
    __shared__ __align__(16) float Ws[16][132];
    const int tid = threadIdx.x;
    const int tx = tid & 15, ty = tid >> 4;
    const int m0 = blockIdx.y * 128, n0 = blockIdx.x * 128;
    const int kbeg = blockIdx.z * 256, kend = kbeg + 256;

    float acc[8][8];
#pragma unroll
    for (int i = 0; i < 8; i++)
#pragma unroll
        for (int j = 0; j < 8; j++) acc[i][j] = 0.f;

    for (int k0 = kbeg; k0 < kend; k0 += 16) {
#pragma unroll
        for (int i = 0; i < 2; i++) {
            int lin = tid + i * 256;
            int row = lin >> 2, k4 = (lin & 3) << 2;
            float4 va = *(const float4*)&h1[(size_t)(m0 + row) * 1024 + k0 + k4];
            As[k4 + 0][row] = va.x; As[k4 + 1][row] = va.y;
            As[k4 + 2][row] = va.z; As[k4 + 3][row] = va.w;
            float4 vw = *(const float4*)&Wh2a[(size_t)(n0 + row) * 1024 + k0 + k4];
            Ws[k4 + 0][row] = vw.x; Ws[k4 + 1][row] = vw.y;
            Ws[k4 + 2][row] = vw.z; Ws[k4 + 3][row] = vw.w;
        }
        __syncthreads();
#pragma unroll
        for (int kk = 0; kk < 16; kk++) {
            float4 a0 = *(const float4*)&As[kk][4 * ty];
            float4 a1 = *(const float4*)&As[kk][64 + 4 * ty];
            float4 b0 = *(const float4*)&Ws[kk][4 * tx];
            float4 b1 = *(const float4*)&Ws[kk][64 + 4 * tx];
            float a[8] = {a0.x, a0.y, a0.z, a0.w, a1.x, a1.y, a1.z, a1.w};
            float b[8] = {b0.x, b0.y, b0.z, b0.w, b1.x, b1.y, b1.z, b1.w};
#pragma unroll
            for (int i = 0; i < 8; i++)
#pragma unroll
                for (int j = 0; j < 8; j++)
                    acc[i][j] = fmaf(a[i], b[j], acc[i][j]);
        }
        __syncthreads();
    }
#pragma unroll
    for (int i = 0; i < 8; i++) {
        int r = (i < 4) ? (4 * ty + i) : (64 + 4 * ty + i - 4);
#pragma unroll
        for (int j = 0; j < 8; j++) {
            int c = (j < 4) ? (4 * tx + j) : (64 + 4 * tx + j - 4);
            atomicAdd(&g_atth[(size_t)(m0 + r) * 512 + n0 + c], acc[i][j]);
        }
    }
}

// ======================================================================
// softmax over S=64 (mask + renorm) + weighted sum of clip -> g_attout
// ======================================================================
__global__ __launch_bounds__(256) void softmax_attout_kernel(
    const float* __restrict__ clip, const int* __restrict__ mask)
{
    const int b = blockIdx.x;
    const int tid = threadIdx.x;
    __shared__ float w[64];
    __shared__ float stat;

    if (tid < 64) w[tid] = g_scores[b * 64 + tid];
    __syncthreads();
    if (tid == 0) {
        float m = w[0];
        for (int s = 1; s < 64; s++) m = fmaxf(m, w[s]);
        stat = m;
    }
    __syncthreads();
    if (tid < 64) w[tid] = expf(w[tid] - stat);
    __syncthreads();
    if (tid == 0) {
        float s = 0.f;
        for (int i = 0; i < 64; i++) s += w[i];
        stat = s;
    }
    __syncthreads();
    if (tid < 64) w[tid] = (w[tid] / stat) * (float)mask[b * 64 + tid];
    __syncthreads();
    if (tid == 0) {
        float s = 0.f;
        for (int i = 0; i < 64; i++) s += w[i];
        stat = s;
    }
    __syncthreads();
    if (tid < 64) w[tid] = w[tid] / stat;
    __syncthreads();

    for (int d = tid; d < 1024; d += 256) {
        float acc = 0.f;
#pragma unroll 8
        for (int s = 0; s < 64; s++)
            acc += w[s] * clip[((size_t)b * 64 + s) * 1024 + d];
        g_attout[(size_t)b * 1024 + d] = acc;
    }
}

// ======================================================================
// LSTM pointwise
// ======================================================================
__global__ __launch_bounds__(256) void lstm_pointwise_kernel(
    const float* __restrict__ state_c, int stream, float* __restrict__ out)
{
    int idx = blockIdx.x * blockDim.x + threadIdx.x;
    int b = idx >> 10, j = idx & 1023;
    const float* g = g_gates + (size_t)b * 4096;
    float ig = 1.f / (1.f + expf(-g[j]));
    float fg = 1.f / (1.f + expf(-g[1024 + j]));
    float gg = tanhf(g[2048 + j]);
    float og = 1.f / (1.f + expf(-g[3072 + j]));
    float c_old = state_c[(size_t)stream * 1048576 + idx];
    float c_new = fg * c_old + ig * gg;
    float h_new = og * tanhf(c_new);
    out[(size_t)b * 2048 + stream * 1024 + j] = h_new;
    out[2097152 + (size_t)stream * 1048576 + idx] = h_new;
    out[4194304 + (size_t)stream * 1048576 + idx] = c_new;
}

// ======================================================================
extern "C" void kernel_launch(void* const* d_in, const int* in_sizes, int n_in,
                              void* d_out, int out_size)
{
    const float* xt       = (const float*)d_in[0];
    const float* event    = (const float*)d_in[2];
    const float* clip     = (const float*)d_in[3];
    const int*   clipmask = (const int*)  d_in[4];
    const float* state_h  = (const float*)d_in[5];
    const float* state_c  = (const float*)d_in[6];
    const float* W_ih0    = (const float*)d_in[7];
    const float* b_ih0    = (const float*)d_in[8];
    const float* W_hh0    = (const float*)d_in[9];
    const float* b_hh0    = (const float*)d_in[10];
    const float* W_ih1    = (const float*)d_in[11];
    const float* b_ih1    = (const float*)d_in[12];
    const float* W_hh1    = (const float*)d_in[13];
    const float* b_hh1    = (const float*)d_in[14];
    const float* W_ctx    = (const float*)d_in[15];
    const float* b_ctx    = (const float*)d_in[16];
    const float* W_h2a    = (const float*)d_in[17];
    const float* b_h2a    = (const float*)d_in[18];
    const float* W_alpha  = (const float*)d_in[19];
    const float* b_alpha  = (const float*)d_in[20];
    float* out = (float*)d_out;

    const float* h0 = state_h;
    const float* h1 = state_h + 1048576;

    const int SMEM_G = 3 * 49152;   // 147456 B (fp16 gates, 3 stages)
    const int SMEM_S = 2 * 55296;   // 110592 B (tf32 scores, 2 stages)
    cudaFuncSetAttribute(fp16_gates_kernel,
                         cudaFuncAttributeMaxDynamicSharedMemorySize, SMEM_G);
    cudaFuncSetAttribute(mma_scores_kernel,
                         cudaFuncAttributeMaxDynamicSharedMemorySize, SMEM_S);

    // ---- operand conversions (fp32 -> fp16) ----
    conv_w_kernel<<<(4096 * 768 + 255) / 256, 256>>>(W_ih0, W_hh0, 0);
    conv_w_kernel<<<(4096 * 768 + 255) / 256, 256>>>(W_ih1, W_hh1, 1);
    conv_a_kernel<<<1024, 256>>>(xt,    0, 0, 0);
    conv_a_kernel<<<1024, 256>>>(event, 0, 0, 1024);
    conv_a_kernel<<<1024, 256>>>(h0,    0, 0, 2048);
    conv_a_kernel<<<1024, 256>>>(xt,    0, 1, 0);
    conv_a_kernel<<<1024, 256>>>(h1,    0, 1, 2048);

    // ---- attention pre-work ----
    init_atth_kernel<<<2048, 256>>>(b_h2a);
    init_scores_kernel<<<256, 256>>>(b_alpha);
    gemm_atth_kernel<<<dim3(4, 8, 4), 256>>>(h1, W_h2a);

    // ---- stream 0 LSTM ----
    fp16_gates_kernel<<<dim3(16, 8), 512, SMEM_G>>>(0, b_ih0, b_hh0);
    lstm_pointwise_kernel<<<4096, 256>>>(state_c, 0, out);

    // ---- attention scores + softmax + context ----
    mma_scores_kernel<<<dim3(2, 512), 512, SMEM_S>>>(clip, W_ctx, b_ctx, W_alpha);
    softmax_attout_kernel<<<1024, 256>>>(clip, clipmask);
    conv_a_kernel<<<1024, 256>>>(nullptr, 1, 1, 1024);   // att -> A1 cols 1024..2047

    // ---- stream 1 LSTM ----
    fp16_gates_kernel<<<dim3(16, 8), 512, SMEM_G>>>(1, b_ih1, b_hh1);
    lstm_pointwise_kernel<<<4096, 256>>>(state_c, 1, out);
}

// round 14
// speedup vs baseline: 2.1674x; 1.4583x over previous
#include <cuda_runtime.h>
#include <cuda_fp16.h>
#include <cstdint>
#include <math.h>

// ---------------- scratch (no allocation allowed) ----------------
__device__ float g_gates[1024 * 4096];     // 16 MB
__device__ float g_atth [1024 * 512];      // 2 MB
__device__ float g_scores[1024 * 64];      // 256 KB
__device__ float g_attout[1024 * 1024];    // 4 MB

// fp16 operands
__device__ __half g_W0[4096 * 3072];
__device__ __half g_W1[4096 * 3072];
__device__ __half g_A0[1024 * 3072];
__device__ __half g_A1[1024 * 3072];
__device__ __half g_clip_h[1024 * 64 * 1024];   // 128 MB
__device__ __half g_Wctx_h[512 * 1024];         // 1 MB

// ================= helpers =================
__device__ __forceinline__ uint32_t smem_u32(const void* p) {
    uint32_t a;
    asm("{ .reg .u64 t; cvta.to.shared.u64 t, %1; cvt.u32.u64 %0, t; }"
        : "=r"(a) : "l"(p));
    return a;
}

#define CP_ASYNC16(dst, src) \
    asm volatile("cp.async.cg.shared.global [%0], [%1], 16;" \
                 :: "r"(dst), "l"(src))
#define CP_COMMIT() asm volatile("cp.async.commit_group;")
#define CP_WAIT2()  asm volatile("cp.async.wait_group 2;")
#define CP_WAIT1()  asm volatile("cp.async.wait_group 1;")
#define CP_WAIT0()  asm volatile("cp.async.wait_group 0;")

#define LDMX4(r0, r1, r2, r3, addr) \
    asm volatile("ldmatrix.sync.aligned.m8n8.x4.shared.b16 {%0,%1,%2,%3}, [%4];" \
                 : "=r"(r0), "=r"(r1), "=r"(r2), "=r"(r3) : "r"(addr))

__device__ __forceinline__ void mma_f16(float* c, const uint32_t* a,
                                        uint32_t b0, uint32_t b1) {
    asm volatile(
        "mma.sync.aligned.m16n8k16.row.col.f32.f16.f16.f32 "
        "{%0,%1,%2,%3}, {%4,%5,%6,%7}, {%8,%9}, {%0,%1,%2,%3};"
        : "+f"(c[0]), "+f"(c[1]), "+f"(c[2]), "+f"(c[3])
        : "r"(a[0]), "r"(a[1]), "r"(a[2]), "r"(a[3]), "r"(b0), "r"(b1));
}

// ================= convert (fp32 -> fp16) kernels =================
__global__ __launch_bounds__(256) void conv_w_kernel(
    const float* __restrict__ Wih, const float* __restrict__ Whh, int which)
{
    __half* dst = which ? g_W1 : g_W0;
    int q = blockIdx.x * blockDim.x + threadIdx.x;      // float4 index
    if (q >= 4096 * 768) return;
    int row = q / 768, c4 = (q - row * 768) * 4;
    float4 v = (c4 < 2048)
        ? *(const float4*)&Wih[(size_t)row * 2048 + c4]
        : *(const float4*)&Whh[(size_t)row * 1024 + (c4 - 2048)];
    __half h[4] = { __float2half(v.x), __float2half(v.y),
                    __float2half(v.z), __float2half(v.w) };
    *(uint2*)&dst[(size_t)row * 3072 + c4] = *(uint2*)h;
}

__global__ __launch_bounds__(256) void conv_a_kernel(
    const float* __restrict__ src, int use_attout, int which, int coloff)
{
    const float* s = use_attout ? g_attout : src;
    __half* dst = which ? g_A1 : g_A0;
    int q = blockIdx.x * blockDim.x + threadIdx.x;      // float4 index
    if (q >= 1024 * 256) return;
    int row = q >> 8, c4 = (q & 255) * 4;
    float4 v = *(const float4*)&s[(size_t)row * 1024 + c4];
    __half h[4] = { __float2half(v.x), __float2half(v.y),
                    __float2half(v.z), __float2half(v.w) };
    *(uint2*)&dst[(size_t)row * 3072 + coloff + c4] = *(uint2*)h;
}

// clip (64M fp32) -> g_clip_h
__global__ __launch_bounds__(256) void conv_clip_kernel(const float* __restrict__ clip)
{
    int q = blockIdx.x * blockDim.x + threadIdx.x;      // float4 index, 16M total
    float4 v = *(const float4*)&clip[(size_t)q * 4];
    __half h[4] = { __float2half(v.x), __float2half(v.y),
                    __float2half(v.z), __float2half(v.w) };
    *(uint2*)&g_clip_h[(size_t)q * 4] = *(uint2*)h;
}

// W_ctx (512x1024 fp32) -> g_Wctx_h
__global__ __launch_bounds__(256) void conv_wctx_kernel(const float* __restrict__ Wctx)
{
    int q = blockIdx.x * blockDim.x + threadIdx.x;      // float4 index, 128K total
    if (q >= 512 * 256) return;
    float4 v = *(const float4*)&Wctx[(size_t)q * 4];
    __half h[4] = { __float2half(v.x), __float2half(v.y),
                    __float2half(v.z), __float2half(v.w) };
    *(uint2*)&g_Wctx_h[(size_t)q * 4] = *(uint2*)h;
}

// ================= tiny init kernels =================
__global__ void init_atth_kernel(const float* __restrict__ b_h2a) {
    int idx = blockIdx.x * blockDim.x + threadIdx.x;
    if (idx < 1024 * 512) g_atth[idx] = b_h2a[idx & 511];
}
__global__ void init_scores_kernel(const float* __restrict__ b_alpha) {
    int idx = blockIdx.x * blockDim.x + threadIdx.x;
    if (idx < 1024 * 64) g_scores[idx] = b_alpha[0];
}

// ======================================================================
// fp16 gates GEMM (validated R12): gates = A@W^T + b_ih + b_hh -> g_gates
// BM=128, BN=256, BK=64 fp16, 3-stage cp.async, ldmatrix + m16n8k16.
// ======================================================================
__global__ void __launch_bounds__(512) fp16_gates_kernel(
    int which, const float* __restrict__ e0, const float* __restrict__ e1)
{
    constexpr int ASZ = 128 * 128;
    constexpr int BSZ = 256 * 128;
    constexpr int STG = ASZ + BSZ;          // 49152
    constexpr int T = 48;                   // 3072 / 64

    const __half* Ah = which ? g_A1 : g_A0;
    const __half* Wh = which ? g_W1 : g_W0;

    extern __shared__ char smc[];
    const uint32_t smu = smem_u32(smc);

    const int tid = threadIdx.x;
    const int lane = tid & 31, w = tid >> 5;
    const int wm = w & 3, wn = w >> 2;
    const int g = lane >> 2, tig = lane & 3;
    const int sub = lane >> 3, sr = lane & 7;
    const int m0 = blockIdx.y * 128, n0 = blockIdx.x * 256;

    float acc[2][8][4];
#pragma unroll
    for (int mt = 0; mt < 2; mt++)
#pragma unroll
        for (int nt = 0; nt < 8; nt++)
#pragma unroll
            for (int r = 0; r < 4; r++) acc[mt][nt][r] = 0.f;

    auto prefetch = [&](int t, int buf) {
        const int kk = t * 64;
        const uint32_t abase = smu + (uint32_t)buf * STG;
        const uint32_t bbase = abase + ASZ;
#pragma unroll
        for (int i = 0; i < 2; i++) {
            int q = tid + i * 512;
            int row = q >> 3, c = q & 7;
            CP_ASYNC16(abase + row * 128 + ((c ^ (row & 7)) << 4),
                       (const void*)&Ah[(size_t)(m0 + row) * 3072 + kk + c * 8]);
        }
#pragma unroll
        for (int i = 0; i < 4; i++) {
            int q = tid + i * 512;
            int row = q >> 3, c = q & 7;
            CP_ASYNC16(bbase + row * 128 + ((c ^ (row & 7)) << 4),
                       (const void*)&Wh[(size_t)(n0 + row) * 3072 + kk + c * 8]);
        }
        CP_COMMIT();
    };

    prefetch(0, 0);
    prefetch(1, 1);

    for (int t = 0; t < T; t++) {
        const int buf = t % 3;
        if (t + 2 < T) { prefetch(t + 2, (t + 2) % 3); CP_WAIT2(); }
        else if (t + 1 < T) { CP_WAIT1(); }
        else { CP_WAIT0(); }
        __syncthreads();

        const uint32_t abase = smu + (uint32_t)buf * STG;
        const uint32_t bbase = abase + ASZ;

#pragma unroll
        for (int s = 0; s < 4; s++) {
            uint32_t a[2][4];
#pragma unroll
            for (int mt = 0; mt < 2; mt++) {
                int r = wm * 32 + mt * 16 + (sub & 1) * 8 + sr;
                int ch = 2 * s + (sub >> 1);
                LDMX4(a[mt][0], a[mt][1], a[mt][2], a[mt][3],
                      abase + r * 128 + ((ch ^ (r & 7)) << 4));
            }
#pragma unroll
            for (int ntp = 0; ntp < 4; ntp++) {
                int r = wn * 64 + ntp * 16 + ((sub >> 1) & 1) * 8 + sr;
                int ch = 2 * s + (sub & 1);
                uint32_t b0, b1, b2, b3;
                LDMX4(b0, b1, b2, b3, bbase + r * 128 + ((ch ^ (r & 7)) << 4));
                mma_f16(acc[0][2 * ntp],     a[0], b0, b1);
                mma_f16(acc[1][2 * ntp],     a[1], b0, b1);
                mma_f16(acc[0][2 * ntp + 1], a[0], b2, b3);
                mma_f16(acc[1][2 * ntp + 1], a[1], b2, b3);
            }
        }
        __syncthreads();
    }

#pragma unroll
    for (int mt = 0; mt < 2; mt++) {
        const int r0 = m0 + wm * 32 + mt * 16 + g;
        const int r1 = r0 + 8;
#pragma unroll
        for (int nt = 0; nt < 8; nt++) {
            const int cb = n0 + wn * 64 + nt * 8 + tig * 2;
            float2 bA = *(const float2*)&e0[cb];
            float2 bB = *(const float2*)&e1[cb];
            const float* a = acc[mt][nt];
            float2 v0 = { a[0] + bA.x + bB.x, a[1] + bA.y + bB.y };
            float2 v1 = { a[2] + bA.x + bB.x, a[3] + bA.y + bB.y };
            *(float2*)&g_gates[(size_t)r0 * 4096 + cb] = v0;
            *(float2*)&g_gates[(size_t)r1 * 4096 + cb] = v1;
        }
    }
}

// ======================================================================
// fp16 scores GEMM (gates-style mainloop, T=16, K=1024):
// scores[b,s] += sum_n Walpha[n]*tanh(clip_h@Wctx_h^T + bctx + atth[b]) (atomic)
// M=65536 (rows b*64+s), N=512; BM=128, BN=256, grid (2, 512).
// ======================================================================
__global__ void __launch_bounds__(512) fp16_scores_kernel(
    const float* __restrict__ e0, const float* __restrict__ e1)
{
    constexpr int ASZ = 128 * 128;
    constexpr int BSZ = 256 * 128;
    constexpr int STG = ASZ + BSZ;
    constexpr int T = 16;                   // 1024 / 64

    extern __shared__ char smc[];
    const uint32_t smu = smem_u32(smc);

    const int tid = threadIdx.x;
    const int lane = tid & 31, w = tid >> 5;
    const int wm = w & 3, wn = w >> 2;
    const int g = lane >> 2, tig = lane & 3;
    const int sub = lane >> 3, sr = lane & 7;
    const int m0 = blockIdx.y * 128, n0 = blockIdx.x * 256;

    float acc[2][8][4];
#pragma unroll
    for (int mt = 0; mt < 2; mt++)
#pragma unroll
        for (int nt = 0; nt < 8; nt++)
#pragma unroll
            for (int r = 0; r < 4; r++) acc[mt][nt][r] = 0.f;

    auto prefetch = [&](int t, int buf) {
        const int kk = t * 64;
        const uint32_t abase = smu + (uint32_t)buf * STG;
        const uint32_t bbase = abase + ASZ;
#pragma unroll
        for (int i = 0; i < 2; i++) {
            int q = tid + i * 512;
            int row = q >> 3, c = q & 7;
            CP_ASYNC16(abase + row * 128 + ((c ^ (row & 7)) << 4),
                       (const void*)&g_clip_h[(size_t)(m0 + row) * 1024 + kk + c * 8]);
        }
#pragma unroll
        for (int i = 0; i < 4; i++) {
            int q = tid + i * 512;
            int row = q >> 3, c = q & 7;
            CP_ASYNC16(bbase + row * 128 + ((c ^ (row & 7)) << 4),
                       (const void*)&g_Wctx_h[(size_t)(n0 + row) * 1024 + kk + c * 8]);
        }
        CP_COMMIT();
    };

    prefetch(0, 0);
    prefetch(1, 1);

    for (int t = 0; t < T; t++) {
        const int buf = t % 3;
        if (t + 2 < T) { prefetch(t + 2, (t + 2) % 3); CP_WAIT2(); }
        else if (t + 1 < T) { CP_WAIT1(); }
        else { CP_WAIT0(); }
        __syncthreads();

        const uint32_t abase = smu + (uint32_t)buf * STG;
        const uint32_t bbase = abase + ASZ;

#pragma unroll
        for (int s = 0; s < 4; s++) {
            uint32_t a[2][4];
#pragma unroll
            for (int mt = 0; mt < 2; mt++) {
                int r = wm * 32 + mt * 16 + (sub & 1) * 8 + sr;
                int ch = 2 * s + (sub >> 1);
                LDMX4(a[mt][0], a[mt][1], a[mt][2], a[mt][3],
                      abase + r * 128 + ((ch ^ (r & 7)) << 4));
            }
#pragma unroll
            for (int ntp = 0; ntp < 4; ntp++) {
                int r = wn * 64 + ntp * 16 + ((sub >> 1) & 1) * 8 + sr;
                int ch = 2 * s + (sub & 1);
                uint32_t b0, b1, b2, b3;
                LDMX4(b0, b1, b2, b3, bbase + r * 128 + ((ch ^ (r & 7)) << 4));
                mma_f16(acc[0][2 * ntp],     a[0], b0, b1);
                mma_f16(acc[1][2 * ntp],     a[1], b0, b1);
                mma_f16(acc[0][2 * ntp + 1], a[0], b2, b3);
                mma_f16(acc[1][2 * ntp + 1], a[1], b2, b3);
            }
        }
        __syncthreads();
    }

    // scores epilogue (validated R12): tanh + W_alpha reduce + atomics
#pragma unroll
    for (int mt = 0; mt < 2; mt++) {
        const int r0 = m0 + wm * 32 + mt * 16 + g;
        const int r1 = r0 + 8;
        const int bb0 = r0 >> 6, bb1 = r1 >> 6;
        float s0 = 0.f, s1 = 0.f;
#pragma unroll
        for (int nt = 0; nt < 8; nt++) {
            const int cb = n0 + wn * 64 + nt * 8 + tig * 2;
            float2 bc = *(const float2*)&e0[cb];
            float2 wa = *(const float2*)&e1[cb];
            float2 a0 = *(const float2*)&g_atth[(size_t)bb0 * 512 + cb];
            float2 a1 = *(const float2*)&g_atth[(size_t)bb1 * 512 + cb];
            const float* a = acc[mt][nt];
            s0 += tanhf(a[0] + bc.x + a0.x) * wa.x + tanhf(a[1] + bc.y + a0.y) * wa.y;
            s1 += tanhf(a[2] + bc.x + a1.x) * wa.x + tanhf(a[3] + bc.y + a1.y) * wa.y;
        }
        s0 += __shfl_xor_sync(0xffffffffu, s0, 1);
        s0 += __shfl_xor_sync(0xffffffffu, s0, 2);
        s1 += __shfl_xor_sync(0xffffffffu, s1, 1);
        s1 += __shfl_xor_sync(0xffffffffu, s1, 2);
        if (tig == 0) {
            atomicAdd(&g_scores[r0], s0);
            atomicAdd(&g_scores[r1], s1);
        }
    }
}

// ======================================================================
// GEMM (small, SIMT): att_h += pre_h1 @ W_h2a^T  (split-K=4)
// ======================================================================
__global__ __launch_bounds__(256) void gemm_atth_kernel(
    const float* __restrict__ h1, const float* __restrict__ Wh2a)
{
    __shared__ __align__(16) float As[16][132];
    __shared__ __align__(16) float Ws[16][132];
    const int tid = threadIdx.x;
    const int tx = tid & 15, ty = tid >> 4;
    const int m0 = blockIdx.y * 128, n0 = blockIdx.x * 128;
    const int kbeg = blockIdx.z * 256, kend = kbeg + 256;

    float acc[8][8];
#pragma unroll
    for (int i = 0; i < 8; i++)
#pragma unroll
        for (int j = 0; j < 8; j++) acc[i][j] = 0.f;

    for (int k0 = kbeg; k0 < kend; k0 += 16) {
#pragma unroll
        for (int i = 0; i < 2; i++) {
            int lin = tid + i * 256;
            int row = lin >> 2, k4 = (lin & 3) << 2;
            float4 va = *(const float4*)&h1[(size_t)(m0 + row) * 1024 + k0 + k4];
            As[k4 + 0][row] = va.x; As[k4 + 1][row] = va.y;
            As[k4 + 2][row] = va.z; As[k4 + 3][row] = va.w;
            float4 vw = *(const float4*)&Wh2a[(size_t)(n0 + row) * 1024 + k0 + k4];
            Ws[k4 + 0][row] = vw.x; Ws[k4 + 1][row] = vw.y;
            Ws[k4 + 2][row] = vw.z; Ws[k4 + 3][row] = vw.w;
        }
        __syncthreads();
#pragma unroll
        for (int kk = 0; kk < 16; kk++) {
            float4 a0 = *(const float4*)&As[kk][4 * ty];
            float4 a1 = *(const float4*)&As[kk][64 + 4 * ty];
            float4 b0 = *(const float4*)&Ws[kk][4 * tx];
            float4 b1 = *(const float4*)&Ws[kk][64 + 4 * tx];
            float a[8] = {a0.x, a0.y, a0.z, a0.w, a1.x, a1.y, a1.z, a1.w};
            float b[8] = {b0.x, b0.y, b0.z, b0.w, b1.x, b1.y, b1.z, b1.w};
#pragma unroll
            for (int i = 0; i < 8; i++)
#pragma unroll
                for (int j = 0; j < 8; j++)
                    acc[i][j] = fmaf(a[i], b[j], acc[i][j]);
        }
        __syncthreads();
    }
#pragma unroll
    for (int i = 0; i < 8; i++) {
        int r = (i < 4) ? (4 * ty + i) : (64 + 4 * ty + i - 4);
#pragma unroll
        for (int j = 0; j < 8; j++) {
            int c = (j < 4) ? (4 * tx + j) : (64 + 4 * tx + j - 4);
            atomicAdd(&g_atth[(size_t)(m0 + r) * 512 + n0 + c], acc[i][j]);
        }
    }
}

// ======================================================================
// softmax over S=64 (mask + renorm) + weighted sum of fp16 clip -> g_attout
// ======================================================================
__global__ __launch_bounds__(256) void softmax_attout_kernel(
    const int* __restrict__ mask)
{
    const int b = blockIdx.x;
    const int tid = threadIdx.x;
    __shared__ float w[64];
    __shared__ float stat;

    if (tid < 64) w[tid] = g_scores[b * 64 + tid];
    __syncthreads();
    if (tid == 0) {
        float m = w[0];
        for (int s = 1; s < 64; s++) m = fmaxf(m, w[s]);
        stat = m;
    }
    __syncthreads();
    if (tid < 64) w[tid] = expf(w[tid] - stat);
    __syncthreads();
    if (tid == 0) {
        float s = 0.f;
        for (int i = 0; i < 64; i++) s += w[i];
        stat = s;
    }
    __syncthreads();
    if (tid < 64) w[tid] = (w[tid] / stat) * (float)mask[b * 64 + tid];
    __syncthreads();
    if (tid == 0) {
        float s = 0.f;
        for (int i = 0; i < 64; i++) s += w[i];
        stat = s;
    }
    __syncthreads();
    if (tid < 64) w[tid] = w[tid] / stat;
    __syncthreads();

    // weighted sum over fp16 clip (half2: d2 indexes pairs)
    for (int d2 = tid; d2 < 512; d2 += 256) {
        float a0 = 0.f, a1 = 0.f;
#pragma unroll 8
        for (int s = 0; s < 64; s++) {
            __half2 hv = *(const __half2*)&g_clip_h[((size_t)b * 64 + s) * 1024 + d2 * 2];
            float2 f = __half22float2(hv);
            a0 += w[s] * f.x;
            a1 += w[s] * f.y;
        }
        g_attout[(size_t)b * 1024 + d2 * 2]     = a0;
        g_attout[(size_t)b * 1024 + d2 * 2 + 1] = a1;
    }
}

// ======================================================================
// LSTM pointwise
// ======================================================================
__global__ __launch_bounds__(256) void lstm_pointwise_kernel(
    const float* __restrict__ state_c, int stream, float* __restrict__ out)
{
    int idx = blockIdx.x * blockDim.x + threadIdx.x;
    int b = idx >> 10, j = idx & 1023;
    const float* g = g_gates + (size_t)b * 4096;
    float ig = 1.f / (1.f + expf(-g[j]));
    float fg = 1.f / (1.f + expf(-g[1024 + j]));
    float gg = tanhf(g[2048 + j]);
    float og = 1.f / (1.f + expf(-g[3072 + j]));
    float c_old = state_c[(size_t)stream * 1048576 + idx];
    float c_new = fg * c_old + ig * gg;
    float h_new = og * tanhf(c_new);
    out[(size_t)b * 2048 + stream * 1024 + j] = h_new;
    out[2097152 + (size_t)stream * 1048576 + idx] = h_new;
    out[4194304 + (size_t)stream * 1048576 + idx] = c_new;
}

// ======================================================================
extern "C" void kernel_launch(void* const* d_in, const int* in_sizes, int n_in,
                              void* d_out, int out_size)
{
    const float* xt       = (const float*)d_in[0];
    const float* event    = (const float*)d_in[2];
    const float* clip     = (const float*)d_in[3];
    const int*   clipmask = (const int*)  d_in[4];
    const float* state_h  = (const float*)d_in[5];
    const float* state_c  = (const float*)d_in[6];
    const float* W_ih0    = (const float*)d_in[7];
    const float* b_ih0    = (const float*)d_in[8];
    const float* W_hh0    = (const float*)d_in[9];
    const float* b_hh0    = (const float*)d_in[10];
    const float* W_ih1    = (const float*)d_in[11];
    const float* b_ih1    = (const float*)d_in[12];
    const float* W_hh1    = (const float*)d_in[13];
    const float* b_hh1    = (const float*)d_in[14];
    const float* W_ctx    = (const float*)d_in[15];
    const float* b_ctx    = (const float*)d_in[16];
    const float* W_h2a    = (const float*)d_in[17];
    const float* b_h2a    = (const float*)d_in[18];
    const float* W_alpha  = (const float*)d_in[19];
    const float* b_alpha  = (const float*)d_in[20];
    float* out = (float*)d_out;

    const float* h0 = state_h;
    const float* h1 = state_h + 1048576;

    const int SMEM_G = 3 * 49152;   // 147456 B (3-stage fp16)
    cudaFuncSetAttribute(fp16_gates_kernel,
                         cudaFuncAttributeMaxDynamicSharedMemorySize, SMEM_G);
    cudaFuncSetAttribute(fp16_scores_kernel,
                         cudaFuncAttributeMaxDynamicSharedMemorySize, SMEM_G);

    // ---- operand conversions (fp32 -> fp16) ----
    conv_clip_kernel<<<65536, 256>>>(clip);           // 16M float4
    conv_wctx_kernel<<<512, 256>>>(W_ctx);
    conv_w_kernel<<<(4096 * 768 + 255) / 256, 256>>>(W_ih0, W_hh0, 0);
    conv_w_kernel<<<(4096 * 768 + 255) / 256, 256>>>(W_ih1, W_hh1, 1);
    conv_a_kernel<<<1024, 256>>>(xt,    0, 0, 0);
    conv_a_kernel<<<1024, 256>>>(event, 0, 0, 1024);
    conv_a_kernel<<<1024, 256>>>(h0,    0, 0, 2048);
    conv_a_kernel<<<1024, 256>>>(xt,    0, 1, 0);
    conv_a_kernel<<<1024, 256>>>(h1,    0, 1, 2048);

    // ---- attention pre-work ----
    init_atth_kernel<<<2048, 256>>>(b_h2a);
    init_scores_kernel<<<256, 256>>>(b_alpha);
    gemm_atth_kernel<<<dim3(4, 8, 4), 256>>>(h1, W_h2a);

    // ---- stream 0 LSTM ----
    fp16_gates_kernel<<<dim3(16, 8), 512, SMEM_G>>>(0, b_ih0, b_hh0);
    lstm_pointwise_kernel<<<4096, 256>>>(state_c, 0, out);

    // ---- attention scores + softmax + context ----
    fp16_scores_kernel<<<dim3(2, 512), 512, SMEM_G>>>(b_ctx, W_alpha);
    softmax_attout_kernel<<<1024, 256>>>(clipmask);
    conv_a_kernel<<<1024, 256>>>(nullptr, 1, 1, 1024);   // att -> A1 cols 1024..2047

    // ---- stream 1 LSTM ----
    fp16_gates_kernel<<<dim3(16, 8), 512, SMEM_G>>>(1, b_ih1, b_hh1);
    lstm_pointwise_kernel<<<4096, 256>>>(state_c, 1, out);
}

// round 16
// speedup vs baseline: 2.1739x; 1.0030x over previous
#include <cuda_runtime.h>
#include <cuda_fp16.h>
#include <cstdint>
#include <math.h>

// ---------------- scratch (no allocation allowed) ----------------
__device__ float g_gates[1024 * 4096];     // 16 MB
__device__ float g_atth [1024 * 512];      // 2 MB

// fp16 operands
__device__ __half g_W0[4096 * 3072];
__device__ __half g_W1[4096 * 3072];
__device__ __half g_A0[1024 * 3072];
__device__ __half g_A1[1024 * 3072];
__device__ __half g_Wctx_h[512 * 1024];    // 1 MB

// ================= helpers =================
__device__ __forceinline__ uint32_t smem_u32(const void* p) {
    uint32_t a;
    asm("{ .reg .u64 t; cvta.to.shared.u64 t, %1; cvt.u32.u64 %0, t; }"
        : "=r"(a) : "l"(p));
    return a;
}

#define CP_ASYNC16(dst, src) \
    asm volatile("cp.async.cg.shared.global [%0], [%1], 16;" \
                 :: "r"(dst), "l"(src))
#define CP_COMMIT() asm volatile("cp.async.commit_group;")
#define CP_WAIT2()  asm volatile("cp.async.wait_group 2;")
#define CP_WAIT1()  asm volatile("cp.async.wait_group 1;")
#define CP_WAIT0()  asm volatile("cp.async.wait_group 0;")

#define LDMX4(r0, r1, r2, r3, addr) \
    asm volatile("ldmatrix.sync.aligned.m8n8.x4.shared.b16 {%0,%1,%2,%3}, [%4];" \
                 : "=r"(r0), "=r"(r1), "=r"(r2), "=r"(r3) : "r"(addr))

__device__ __forceinline__ void mma_f16(float* c, const uint32_t* a,
                                        uint32_t b0, uint32_t b1) {
    asm volatile(
        "mma.sync.aligned.m16n8k16.row.col.f32.f16.f16.f32 "
        "{%0,%1,%2,%3}, {%4,%5,%6,%7}, {%8,%9}, {%0,%1,%2,%3};"
        : "+f"(c[0]), "+f"(c[1]), "+f"(c[2]), "+f"(c[3])
        : "r"(a[0]), "r"(a[1]), "r"(a[2]), "r"(a[3]), "r"(b0), "r"(b1));
}

// ================= convert (fp32 -> fp16) kernels =================
__global__ __launch_bounds__(256) void conv_w_kernel(
    const float* __restrict__ Wih, const float* __restrict__ Whh, int which)
{
    __half* dst = which ? g_W1 : g_W0;
    int q = blockIdx.x * blockDim.x + threadIdx.x;      // float4 index
    if (q >= 4096 * 768) return;
    int row = q / 768, c4 = (q - row * 768) * 4;
    float4 v = (c4 < 2048)
        ? *(const float4*)&Wih[(size_t)row * 2048 + c4]
        : *(const float4*)&Whh[(size_t)row * 1024 + (c4 - 2048)];
    __half h[4] = { __float2half(v.x), __float2half(v.y),
                    __float2half(v.z), __float2half(v.w) };
    *(uint2*)&dst[(size_t)row * 3072 + c4] = *(uint2*)h;
}

__global__ __launch_bounds__(256) void conv_a_kernel(
    const float* __restrict__ src, int which, int coloff)
{
    __half* dst = which ? g_A1 : g_A0;
    int q = blockIdx.x * blockDim.x + threadIdx.x;      // float4 index
    if (q >= 1024 * 256) return;
    int row = q >> 8, c4 = (q & 255) * 4;
    float4 v = *(const float4*)&src[(size_t)row * 1024 + c4];
    __half h[4] = { __float2half(v.x), __float2half(v.y),
                    __float2half(v.z), __float2half(v.w) };
    *(uint2*)&dst[(size_t)row * 3072 + coloff + c4] = *(uint2*)h;
}

__global__ __launch_bounds__(256) void conv_wctx_kernel(const float* __restrict__ Wctx)
{
    int q = blockIdx.x * blockDim.x + threadIdx.x;      // float4 index, 128K total
    if (q >= 512 * 256) return;
    float4 v = *(const float4*)&Wctx[(size_t)q * 4];
    __half h[4] = { __float2half(v.x), __float2half(v.y),
                    __float2half(v.z), __float2half(v.w) };
    *(uint2*)&g_Wctx_h[(size_t)q * 4] = *(uint2*)h;
}

// ================= tiny init kernel =================
__global__ void init_atth_kernel(const float* __restrict__ b_h2a) {
    int idx = blockIdx.x * blockDim.x + threadIdx.x;
    if (idx < 1024 * 512) g_atth[idx] = b_h2a[idx & 511];
}

// ======================================================================
// fp16 gates GEMM (validated R12): gates = A@W^T + b_ih + b_hh -> g_gates
// ======================================================================
__global__ void __launch_bounds__(512) fp16_gates_kernel(
    int which, const float* __restrict__ e0, const float* __restrict__ e1)
{
    constexpr int ASZ = 128 * 128;
    constexpr int BSZ = 256 * 128;
    constexpr int STG = ASZ + BSZ;          // 49152
    constexpr int T = 48;                   // 3072 / 64

    const __half* Ah = which ? g_A1 : g_A0;
    const __half* Wh = which ? g_W1 : g_W0;

    extern __shared__ char smc[];
    const uint32_t smu = smem_u32(smc);

    const int tid = threadIdx.x;
    const int lane = tid & 31, w = tid >> 5;
    const int wm = w & 3, wn = w >> 2;
    const int g = lane >> 2, tig = lane & 3;
    const int sub = lane >> 3, sr = lane & 7;
    const int m0 = blockIdx.y * 128, n0 = blockIdx.x * 256;

    float acc[2][8][4];
#pragma unroll
    for (int mt = 0; mt < 2; mt++)
#pragma unroll
        for (int nt = 0; nt < 8; nt++)
#pragma unroll
            for (int r = 0; r < 4; r++) acc[mt][nt][r] = 0.f;

    auto prefetch = [&](int t, int buf) {
        const int kk = t * 64;
        const uint32_t abase = smu + (uint32_t)buf * STG;
        const uint32_t bbase = abase + ASZ;
#pragma unroll
        for (int i = 0; i < 2; i++) {
            int q = tid + i * 512;
            int row = q >> 3, c = q & 7;
            CP_ASYNC16(abase + row * 128 + ((c ^ (row & 7)) << 4),
                       (const void*)&Ah[(size_t)(m0 + row) * 3072 + kk + c * 8]);
        }
#pragma unroll
        for (int i = 0; i < 4; i++) {
            int q = tid + i * 512;
            int row = q >> 3, c = q & 7;
            CP_ASYNC16(bbase + row * 128 + ((c ^ (row & 7)) << 4),
                       (const void*)&Wh[(size_t)(n0 + row) * 3072 + kk + c * 8]);
        }
        CP_COMMIT();
    };

    prefetch(0, 0);
    prefetch(1, 1);

    for (int t = 0; t < T; t++) {
        const int buf = t % 3;
        if (t + 2 < T) { prefetch(t + 2, (t + 2) % 3); CP_WAIT2(); }
        else if (t + 1 < T) { CP_WAIT1(); }
        else { CP_WAIT0(); }
        __syncthreads();

        const uint32_t abase = smu + (uint32_t)buf * STG;
        const uint32_t bbase = abase + ASZ;

#pragma unroll
        for (int s = 0; s < 4; s++) {
            uint32_t a[2][4];
#pragma unroll
            for (int mt = 0; mt < 2; mt++) {
                int r = wm * 32 + mt * 16 + (sub & 1) * 8 + sr;
                int ch = 2 * s + (sub >> 1);
                LDMX4(a[mt][0], a[mt][1], a[mt][2], a[mt][3],
                      abase + r * 128 + ((ch ^ (r & 7)) << 4));
            }
#pragma unroll
            for (int ntp = 0; ntp < 4; ntp++) {
                int r = wn * 64 + ntp * 16 + ((sub >> 1) & 1) * 8 + sr;
                int ch = 2 * s + (sub & 1);
                uint32_t b0, b1, b2, b3;
                LDMX4(b0, b1, b2, b3, bbase + r * 128 + ((ch ^ (r & 7)) << 4));
                mma_f16(acc[0][2 * ntp],     a[0], b0, b1);
                mma_f16(acc[1][2 * ntp],     a[1], b0, b1);
                mma_f16(acc[0][2 * ntp + 1], a[0], b2, b3);
                mma_f16(acc[1][2 * ntp + 1], a[1], b2, b3);
            }
        }
        __syncthreads();
    }

#pragma unroll
    for (int mt = 0; mt < 2; mt++) {
        const int r0 = m0 + wm * 32 + mt * 16 + g;
        const int r1 = r0 + 8;
#pragma unroll
        for (int nt = 0; nt < 8; nt++) {
            const int cb = n0 + wn * 64 + nt * 8 + tig * 2;
            float2 bA = *(const float2*)&e0[cb];
            float2 bB = *(const float2*)&e1[cb];
            const float* a = acc[mt][nt];
            float2 v0 = { a[0] + bA.x + bB.x, a[1] + bA.y + bB.y };
            float2 v1 = { a[2] + bA.x + bB.x, a[3] + bA.y + bB.y };
            *(float2*)&g_gates[(size_t)r0 * 4096 + cb] = v0;
            *(float2*)&g_gates[(size_t)r1 * 4096 + cb] = v1;
        }
    }
}

// ======================================================================
// Fused attention: one block per batch b (grid 1024, 512 thr, 224 KB smem).
// RACE FIX vs R15: __syncthreads() between CP_WAIT and the stage->clipT
// conversion (cp.async completion is only visible cross-thread after a barrier).
// ======================================================================
__global__ void __launch_bounds__(512) fused_attn_kernel(
    const float* __restrict__ clip, const int* __restrict__ mask,
    const float* __restrict__ bctx, const float* __restrict__ walpha)
{
    extern __shared__ char smc[];
    const uint32_t smu = smem_u32(smc);
    const uint32_t CLIPT = smu;               // 64 x 2048 B (fp16, swizzled)
    const uint32_t WBUF  = smu + 131072;      // 2 x (256 x 128 B)
    const uint32_t STAGE = smu + 196608;      // 2 x (64 x 256 B fp32)
    float* red = (float*)(smc + 196608);      // [8][64] (overlays stage post-loop)
    float* wsm = (float*)(smc + 196608 + 2048);

    const int b   = blockIdx.x;
    const int tid = threadIdx.x;
    const int lane = tid & 31, w = tid >> 5;
    const int wm = w & 1, wn = w >> 1;        // 2 m-warps x 8 n-warps
    const int g = lane >> 2, tig = lane & 3;
    const int sub = lane >> 3, sr = lane & 7;

    float part[4] = {0.f, 0.f, 0.f, 0.f};
    float acc[2][4][4];

    auto issue = [&](int u) {
        const int p = u >> 4, t = u & 15, buf = u & 1;
        const uint32_t wb = WBUF + (uint32_t)buf * 32768;
#pragma unroll
        for (int i = 0; i < 4; i++) {            // W: 2048 chunks / 512 thr
            int q = tid + i * 512;
            int row = q >> 3, c = q & 7;
            CP_ASYNC16(wb + row * 128 + ((c ^ (row & 7)) << 4),
                (const void*)&g_Wctx_h[(size_t)(p * 256 + row) * 1024 + t * 64 + c * 8]);
        }
        if (u < 16) {                            // clip fp32 stage: 1024 f4
            const uint32_t st = STAGE + (uint32_t)buf * 16384;
#pragma unroll
            for (int i = 0; i < 2; i++) {
                int q = tid + i * 512;
                int row = q >> 4, c4 = q & 15;
                CP_ASYNC16(st + row * 256 + c4 * 16,
                    (const void*)&clip[((size_t)b * 64 + row) * 1024 + t * 64 + c4 * 4]);
            }
        }
        CP_COMMIT();
    };

    issue(0);

    for (int u = 0; u < 32; u++) {
        const int t = u & 15;
        if (t == 0) {
#pragma unroll
            for (int mt = 0; mt < 2; mt++)
#pragma unroll
                for (int nt = 0; nt < 4; nt++)
#pragma unroll
                    for (int r = 0; r < 4; r++) acc[mt][nt][r] = 0.f;
        }
        __syncthreads();                         // prev GEMM done; buffers reusable
        if (u + 1 < 32) { issue(u + 1); CP_WAIT1(); }
        else { CP_WAIT0(); }
        __syncthreads();                         // group-u copies visible to ALL threads
        if (u < 16) {
            // convert stage u -> clipT chunk u (each thread: one 16B fp16 chunk)
            const uint32_t stoff = 196608 + (uint32_t)(u & 1) * 16384;
            const int row = tid >> 3, cc = tid & 7;
            float4 v0 = *(const float4*)(smc + stoff + row * 256 + cc * 32);
            float4 v1 = *(const float4*)(smc + stoff + row * 256 + cc * 32 + 16);
            __half h[8] = { __float2half(v0.x), __float2half(v0.y),
                            __float2half(v0.z), __float2half(v0.w),
                            __float2half(v1.x), __float2half(v1.y),
                            __float2half(v1.z), __float2half(v1.w) };
            const int ck = u * 8 + cc;
            *(uint4*)(smc + row * 2048 + ((ck ^ (row & 7)) << 4)) = *(uint4*)h;
        }
        __syncthreads();                         // clipT chunk ready for ldmatrix

        const uint32_t wb = WBUF + (uint32_t)(u & 1) * 32768;
#pragma unroll
        for (int s = 0; s < 4; s++) {
            uint32_t a[2][4];
#pragma unroll
            for (int mt = 0; mt < 2; mt++) {
                int r = wm * 32 + mt * 16 + (sub & 1) * 8 + sr;
                int ch = t * 8 + 2 * s + (sub >> 1);
                LDMX4(a[mt][0], a[mt][1], a[mt][2], a[mt][3],
                      CLIPT + r * 2048 + ((ch ^ (r & 7)) << 4));
            }
#pragma unroll
            for (int ntp = 0; ntp < 2; ntp++) {
                int r = wn * 32 + ntp * 16 + ((sub >> 1) & 1) * 8 + sr;
                int lc = 2 * s + (sub & 1);
                uint32_t b0, b1, b2, b3;
                LDMX4(b0, b1, b2, b3, wb + r * 128 + ((lc ^ (r & 7)) << 4));
                mma_f16(acc[0][2 * ntp],     a[0], b0, b1);
                mma_f16(acc[1][2 * ntp],     a[1], b0, b1);
                mma_f16(acc[0][2 * ntp + 1], a[0], b2, b3);
                mma_f16(acc[1][2 * ntp + 1], a[1], b2, b3);
            }
        }

        if (t == 15) {
            const int p = u >> 4;
#pragma unroll
            for (int mt = 0; mt < 2; mt++)
#pragma unroll
                for (int nt = 0; nt < 4; nt++) {
                    int n = p * 256 + wn * 32 + nt * 8 + tig * 2;
                    float2 bc = *(const float2*)&bctx[n];
                    float2 wa = *(const float2*)&walpha[n];
                    float2 ah = *(const float2*)&g_atth[(size_t)b * 512 + n];
                    const float* a = acc[mt][nt];
                    part[mt * 2 + 0] += tanhf(a[0] + bc.x + ah.x) * wa.x
                                      + tanhf(a[1] + bc.y + ah.y) * wa.y;
                    part[mt * 2 + 1] += tanhf(a[2] + bc.x + ah.x) * wa.x
                                      + tanhf(a[3] + bc.y + ah.y) * wa.y;
                }
        }
    }

    // quad reduce (lanes of same rows), then cross-warp via smem
#pragma unroll
    for (int i = 0; i < 4; i++) {
        part[i] += __shfl_xor_sync(0xffffffffu, part[i], 1);
        part[i] += __shfl_xor_sync(0xffffffffu, part[i], 2);
    }
    __syncthreads();                             // stage area now reusable as red
    if (tig == 0) {
        red[wn * 64 + wm * 32 + g]      = part[0];
        red[wn * 64 + wm * 32 + 8 + g]  = part[1];
        red[wn * 64 + wm * 32 + 16 + g] = part[2];
        red[wn * 64 + wm * 32 + 24 + g] = part[3];
    }
    __syncthreads();

    // masked softmax over 64 scores (warp 0; exp*mask / sum — algebraically
    // identical to softmax -> mask -> renormalize; b_alpha shift cancels)
    if (tid < 32) {
        float x0 = 0.f, x1 = 0.f;
#pragma unroll
        for (int j = 0; j < 8; j++) {
            x0 += red[j * 64 + tid];
            x1 += red[j * 64 + 32 + tid];
        }
        float mx = fmaxf(x0, x1);
#pragma unroll
        for (int o = 16; o > 0; o >>= 1) mx = fmaxf(mx, __shfl_xor_sync(0xffffffffu, mx, o));
        x0 = expf(x0 - mx) * (float)mask[b * 64 + tid];
        x1 = expf(x1 - mx) * (float)mask[b * 64 + 32 + tid];
        float sm = x0 + x1;
#pragma unroll
        for (int o = 16; o > 0; o >>= 1) sm += __shfl_xor_sync(0xffffffffu, sm, o);
        float inv = 1.f / sm;
        wsm[tid] = x0 * inv;
        wsm[tid + 32] = x1 * inv;
    }
    __syncthreads();

    // context: attout[d] = sum_s w[s]*clipT[s][d]; write fp16 -> g_A1 cols 1024..2047
    {
        const int d2 = tid;                      // 0..511 (half2 pairs)
        const int ck = d2 >> 2;
        float a0 = 0.f, a1 = 0.f;
#pragma unroll 8
        for (int s = 0; s < 64; s++) {
            const __half2 hv = *(const __half2*)(
                smc + s * 2048 + ((ck ^ (s & 7)) << 4) + (d2 & 3) * 4);
            float2 f = __half22float2(hv);
            float ws = wsm[s];
            a0 += ws * f.x;
            a1 += ws * f.y;
        }
        __half2 hv;
        ((__half*)&hv)[0] = __float2half(a0);
        ((__half*)&hv)[1] = __float2half(a1);
        *(__half2*)&g_A1[(size_t)b * 3072 + 1024 + d2 * 2] = hv;
    }
}

// ======================================================================
// GEMM (small, SIMT): att_h += pre_h1 @ W_h2a^T  (split-K=4)
// ======================================================================
__global__ __launch_bounds__(256) void gemm_atth_kernel(
    const float* __restrict__ h1, const float* __restrict__ Wh2a)
{
    __shared__ __align__(16) float As[16][132];
    __shared__ __align__(16) float Ws[16][132];
    const int tid = threadIdx.x;
    const int tx = tid & 15, ty = tid >> 4;
    const int m0 = blockIdx.y * 128, n0 = blockIdx.x * 128;
    const int kbeg = blockIdx.z * 256, kend = kbeg + 256;

    float acc[8][8];
#pragma unroll
    for (int i = 0; i < 8; i++)
#pragma unroll
        for (int j = 0; j < 8; j++) acc[i][j] = 0.f;

    for (int k0 = kbeg; k0 < kend; k0 += 16) {
#pragma unroll
        for (int i = 0; i < 2; i++) {
            int lin = tid + i * 256;
            int row = lin >> 2, k4 = (lin & 3) << 2;
            float4 va = *(const float4*)&h1[(size_t)(m0 + row) * 1024 + k0 + k4];
            As[k4 + 0][row] = va.x; As[k4 + 1][row] = va.y;
            As[k4 + 2][row] = va.z; As[k4 + 3][row] = va.w;
            float4 vw = *(const float4*)&Wh2a[(size_t)(n0 + row) * 1024 + k0 + k4];
            Ws[k4 + 0][row] = vw.x; Ws[k4 + 1][row] = vw.y;
            Ws[k4 + 2][row] = vw.z; Ws[k4 + 3][row] = vw.w;
        }
        __syncthreads();
#pragma unroll
        for (int kk = 0; kk < 16; kk++) {
            float4 a0 = *(const float4*)&As[kk][4 * ty];
            float4 a1 = *(const float4*)&As[kk][64 + 4 * ty];
            float4 b0 = *(const float4*)&Ws[kk][4 * tx];
            float4 b1 = *(const float4*)&Ws[kk][64 + 4 * tx];
            float a[8] = {a0.x, a0.y, a0.z, a0.w, a1.x, a1.y, a1.z, a1.w};
            float b[8] = {b0.x, b0.y, b0.z, b0.w, b1.x, b1.y, b1.z, b1.w};
#pragma unroll
            for (int i = 0; i < 8; i++)
#pragma unroll
                for (int j = 0; j < 8; j++)
                    acc[i][j] = fmaf(a[i], b[j], acc[i][j]);
        }
        __syncthreads();
    }
#pragma unroll
    for (int i = 0; i < 8; i++) {
        int r = (i < 4) ? (4 * ty + i) : (64 + 4 * ty + i - 4);
#pragma unroll
        for (int j = 0; j < 8; j++) {
            int c = (j < 4) ? (4 * tx + j) : (64 + 4 * tx + j - 4);
            atomicAdd(&g_atth[(size_t)(m0 + r) * 512 + n0 + c], acc[i][j]);
        }
    }
}

// ======================================================================
// LSTM pointwise
// ======================================================================
__global__ __launch_bounds__(256) void lstm_pointwise_kernel(
    const float* __restrict__ state_c, int stream, float* __restrict__ out)
{
    int idx = blockIdx.x * blockDim.x + threadIdx.x;
    int b = idx >> 10, j = idx & 1023;
    const float* g = g_gates + (size_t)b * 4096;
    float ig = 1.f / (1.f + expf(-g[j]));
    float fg = 1.f / (1.f + expf(-g[1024 + j]));
    float gg = tanhf(g[2048 + j]);
    float og = 1.f / (1.f + expf(-g[3072 + j]));
    float c_old = state_c[(size_t)stream * 1048576 + idx];
    float c_new = fg * c_old + ig * gg;
    float h_new = og * tanhf(c_new);
    out[(size_t)b * 2048 + stream * 1024 + j] = h_new;
    out[2097152 + (size_t)stream * 1048576 + idx] = h_new;
    out[4194304 + (size_t)stream * 1048576 + idx] = c_new;
}

// ======================================================================
extern "C" void kernel_launch(void* const* d_in, const int* in_sizes, int n_in,
                              void* d_out, int out_size)
{
    const float* xt       = (const float*)d_in[0];
    const float* event    = (const float*)d_in[2];
    const float* clip     = (const float*)d_in[3];
    const int*   clipmask = (const int*)  d_in[4];
    const float* state_h  = (const float*)d_in[5];
    const float* state_c  = (const float*)d_in[6];
    const float* W_ih0    = (const float*)d_in[7];
    const float* b_ih0    = (const float*)d_in[8];
    const float* W_hh0    = (const float*)d_in[9];
    const float* b_hh0    = (const float*)d_in[10];
    const float* W_ih1    = (const float*)d_in[11];
    const float* b_ih1    = (const float*)d_in[12];
    const float* W_hh1    = (const float*)d_in[13];
    const float* b_hh1    = (const float*)d_in[14];
    const float* W_ctx    = (const float*)d_in[15];
    const float* b_ctx    = (const float*)d_in[16];
    const float* W_h2a    = (const float*)d_in[17];
    const float* b_h2a    = (const float*)d_in[18];
    const float* W_alpha  = (const float*)d_in[19];
    float* out = (float*)d_out;

    const float* h0 = state_h;
    const float* h1 = state_h + 1048576;

    const int SMEM_G = 3 * 49152;   // 147456 B (gates, 3-stage fp16)
    const int SMEM_F = 229376;      // fused attention (224 KB)
    cudaFuncSetAttribute(fp16_gates_kernel,
                         cudaFuncAttributeMaxDynamicSharedMemorySize, SMEM_G);
    cudaFuncSetAttribute(fused_attn_kernel,
                         cudaFuncAttributeMaxDynamicSharedMemorySize, SMEM_F);

    // ---- operand conversions (fp32 -> fp16) ----
    conv_wctx_kernel<<<512, 256>>>(W_ctx);
    conv_w_kernel<<<(4096 * 768 + 255) / 256, 256>>>(W_ih0, W_hh0, 0);
    conv_w_kernel<<<(4096 * 768 + 255) / 256, 256>>>(W_ih1, W_hh1, 1);
    conv_a_kernel<<<1024, 256>>>(xt,    0, 0);
    conv_a_kernel<<<1024, 256>>>(event, 0, 1024);
    conv_a_kernel<<<1024, 256>>>(h0,    0, 2048);
    conv_a_kernel<<<1024, 256>>>(xt,    1, 0);
    conv_a_kernel<<<1024, 256>>>(h1,    1, 2048);

    // ---- attention pre-work ----
    init_atth_kernel<<<2048, 256>>>(b_h2a);
    gemm_atth_kernel<<<dim3(4, 8, 4), 256>>>(h1, W_h2a);

    // ---- stream 0 LSTM ----
    fp16_gates_kernel<<<dim3(16, 8), 512, SMEM_G>>>(0, b_ih0, b_hh0);
    lstm_pointwise_kernel<<<4096, 256>>>(state_c, 0, out);

    // ---- fused attention (scores GEMM + softmax + context -> g_A1 cols 1024..2047) ----
    fused_attn_kernel<<<1024, 512, SMEM_F>>>(clip, clipmask, b_ctx, W_alpha);

    // ---- stream 1 LSTM ----
    fp16_gates_kernel<<<dim3(16, 8), 512, SMEM_G>>>(1, b_ih1, b_hh1);
    lstm_pointwise_kernel<<<4096, 256>>>(state_c, 1, out);
}

// round 17
// speedup vs baseline: 2.2424x; 1.0315x over previous
#include <cuda_runtime.h>
#include <cuda_fp16.h>
#include <cstdint>
#include <math.h>

// ---------------- scratch (no allocation allowed) ----------------
__device__ float g_gates[1024 * 4096];     // 16 MB
__device__ float g_atth [1024 * 512];      // 2 MB
__device__ float g_scores[1024 * 64];      // 256 KB

// fp16 operands
__device__ __half g_W0[4096 * 3072];
__device__ __half g_W1[4096 * 3072];
__device__ __half g_A0[1024 * 3072];
__device__ __half g_A1[1024 * 3072];
__device__ __half g_Wctx_h[512 * 1024];    // 1 MB
__device__ __half g_Wh2a_h[512 * 1024];    // 1 MB

// ================= helpers =================
__device__ __forceinline__ uint32_t smem_u32(const void* p) {
    uint32_t a;
    asm("{ .reg .u64 t; cvta.to.shared.u64 t, %1; cvt.u32.u64 %0, t; }"
        : "=r"(a) : "l"(p));
    return a;
}

#define CP_ASYNC16(dst, src) \
    asm volatile("cp.async.cg.shared.global [%0], [%1], 16;" \
                 :: "r"(dst), "l"(src))
#define CP_COMMIT() asm volatile("cp.async.commit_group;")
#define CP_WAIT2()  asm volatile("cp.async.wait_group 2;")
#define CP_WAIT1()  asm volatile("cp.async.wait_group 1;")
#define CP_WAIT0()  asm volatile("cp.async.wait_group 0;")

#define LDMX4(r0, r1, r2, r3, addr) \
    asm volatile("ldmatrix.sync.aligned.m8n8.x4.shared.b16 {%0,%1,%2,%3}, [%4];" \
                 : "=r"(r0), "=r"(r1), "=r"(r2), "=r"(r3) : "r"(addr))

__device__ __forceinline__ void mma_f16(float* c, const uint32_t* a,
                                        uint32_t b0, uint32_t b1) {
    asm volatile(
        "mma.sync.aligned.m16n8k16.row.col.f32.f16.f16.f32 "
        "{%0,%1,%2,%3}, {%4,%5,%6,%7}, {%8,%9}, {%0,%1,%2,%3};"
        : "+f"(c[0]), "+f"(c[1]), "+f"(c[2]), "+f"(c[3])
        : "r"(a[0]), "r"(a[1]), "r"(a[2]), "r"(a[3]), "r"(b0), "r"(b1));
}

// ================= convert (fp32 -> fp16) kernels =================
__global__ __launch_bounds__(256) void conv_w_kernel(
    const float* __restrict__ Wih, const float* __restrict__ Whh, int which)
{
    __half* dst = which ? g_W1 : g_W0;
    int q = blockIdx.x * blockDim.x + threadIdx.x;      // float4 index
    if (q >= 4096 * 768) return;
    int row = q / 768, c4 = (q - row * 768) * 4;
    float4 v = (c4 < 2048)
        ? *(const float4*)&Wih[(size_t)row * 2048 + c4]
        : *(const float4*)&Whh[(size_t)row * 1024 + (c4 - 2048)];
    __half h[4] = { __float2half(v.x), __float2half(v.y),
                    __float2half(v.z), __float2half(v.w) };
    *(uint2*)&dst[(size_t)row * 3072 + c4] = *(uint2*)h;
}

__global__ __launch_bounds__(256) void conv_a_kernel(
    const float* __restrict__ src, int which, int coloff)
{
    __half* dst = which ? g_A1 : g_A0;
    int q = blockIdx.x * blockDim.x + threadIdx.x;      // float4 index
    if (q >= 1024 * 256) return;
    int row = q >> 8, c4 = (q & 255) * 4;
    float4 v = *(const float4*)&src[(size_t)row * 1024 + c4];
    __half h[4] = { __float2half(v.x), __float2half(v.y),
                    __float2half(v.z), __float2half(v.w) };
    *(uint2*)&dst[(size_t)row * 3072 + coloff + c4] = *(uint2*)h;
}

// 512x1024 fp32 -> fp16 (W_ctx or W_h2a)
__global__ __launch_bounds__(256) void conv_w512_kernel(
    const float* __restrict__ W, int which)
{
    __half* dst = which ? g_Wh2a_h : g_Wctx_h;
    int q = blockIdx.x * blockDim.x + threadIdx.x;      // float4 index, 128K total
    if (q >= 512 * 256) return;
    float4 v = *(const float4*)&W[(size_t)q * 4];
    __half h[4] = { __float2half(v.x), __float2half(v.y),
                    __float2half(v.z), __float2half(v.w) };
    *(uint2*)&dst[(size_t)q * 4] = *(uint2*)h;
}

__global__ void init_scores_kernel(const float* __restrict__ b_alpha) {
    int idx = blockIdx.x * blockDim.x + threadIdx.x;
    if (idx < 1024 * 64) g_scores[idx] = b_alpha[0];
}

// ======================================================================
// fp16 gates GEMM (validated R12): gates = A@W^T + b_ih + b_hh -> g_gates
// ======================================================================
__global__ void __launch_bounds__(512) fp16_gates_kernel(
    int which, const float* __restrict__ e0, const float* __restrict__ e1)
{
    constexpr int ASZ = 128 * 128;
    constexpr int BSZ = 256 * 128;
    constexpr int STG = ASZ + BSZ;          // 49152
    constexpr int T = 48;                   // 3072 / 64

    const __half* Ah = which ? g_A1 : g_A0;
    const __half* Wh = which ? g_W1 : g_W0;

    extern __shared__ char smc[];
    const uint32_t smu = smem_u32(smc);

    const int tid = threadIdx.x;
    const int lane = tid & 31, w = tid >> 5;
    const int wm = w & 3, wn = w >> 2;
    const int g = lane >> 2, tig = lane & 3;
    const int sub = lane >> 3, sr = lane & 7;
    const int m0 = blockIdx.y * 128, n0 = blockIdx.x * 256;

    float acc[2][8][4];
#pragma unroll
    for (int mt = 0; mt < 2; mt++)
#pragma unroll
        for (int nt = 0; nt < 8; nt++)
#pragma unroll
            for (int r = 0; r < 4; r++) acc[mt][nt][r] = 0.f;

    auto prefetch = [&](int t, int buf) {
        const int kk = t * 64;
        const uint32_t abase = smu + (uint32_t)buf * STG;
        const uint32_t bbase = abase + ASZ;
#pragma unroll
        for (int i = 0; i < 2; i++) {
            int q = tid + i * 512;
            int row = q >> 3, c = q & 7;
            CP_ASYNC16(abase + row * 128 + ((c ^ (row & 7)) << 4),
                       (const void*)&Ah[(size_t)(m0 + row) * 3072 + kk + c * 8]);
        }
#pragma unroll
        for (int i = 0; i < 4; i++) {
            int q = tid + i * 512;
            int row = q >> 3, c = q & 7;
            CP_ASYNC16(bbase + row * 128 + ((c ^ (row & 7)) << 4),
                       (const void*)&Wh[(size_t)(n0 + row) * 3072 + kk + c * 8]);
        }
        CP_COMMIT();
    };

    prefetch(0, 0);
    prefetch(1, 1);

    for (int t = 0; t < T; t++) {
        const int buf = t % 3;
        if (t + 2 < T) { prefetch(t + 2, (t + 2) % 3); CP_WAIT2(); }
        else if (t + 1 < T) { CP_WAIT1(); }
        else { CP_WAIT0(); }
        __syncthreads();

        const uint32_t abase = smu + (uint32_t)buf * STG;
        const uint32_t bbase = abase + ASZ;

#pragma unroll
        for (int s = 0; s < 4; s++) {
            uint32_t a[2][4];
#pragma unroll
            for (int mt = 0; mt < 2; mt++) {
                int r = wm * 32 + mt * 16 + (sub & 1) * 8 + sr;
                int ch = 2 * s + (sub >> 1);
                LDMX4(a[mt][0], a[mt][1], a[mt][2], a[mt][3],
                      abase + r * 128 + ((ch ^ (r & 7)) << 4));
            }
#pragma unroll
            for (int ntp = 0; ntp < 4; ntp++) {
                int r = wn * 64 + ntp * 16 + ((sub >> 1) & 1) * 8 + sr;
                int ch = 2 * s + (sub & 1);
                uint32_t b0, b1, b2, b3;
                LDMX4(b0, b1, b2, b3, bbase + r * 128 + ((ch ^ (r & 7)) << 4));
                mma_f16(acc[0][2 * ntp],     a[0], b0, b1);
                mma_f16(acc[1][2 * ntp],     a[1], b0, b1);
                mma_f16(acc[0][2 * ntp + 1], a[0], b2, b3);
                mma_f16(acc[1][2 * ntp + 1], a[1], b2, b3);
            }
        }
        __syncthreads();
    }

#pragma unroll
    for (int mt = 0; mt < 2; mt++) {
        const int r0 = m0 + wm * 32 + mt * 16 + g;
        const int r1 = r0 + 8;
#pragma unroll
        for (int nt = 0; nt < 8; nt++) {
            const int cb = n0 + wn * 64 + nt * 8 + tig * 2;
            float2 bA = *(const float2*)&e0[cb];
            float2 bB = *(const float2*)&e1[cb];
            const float* a = acc[mt][nt];
            float2 v0 = { a[0] + bA.x + bB.x, a[1] + bA.y + bB.y };
            float2 v1 = { a[2] + bA.x + bB.x, a[3] + bA.y + bB.y };
            *(float2*)&g_gates[(size_t)r0 * 4096 + cb] = v0;
            *(float2*)&g_gates[(size_t)r1 * 4096 + cb] = v1;
        }
    }
}

// ======================================================================
// fp16 atth GEMM (gates clone, T=16): g_atth = h1_fp16 @ Wh2a^T + b_h2a
// M=1024 (A = g_A1 cols 2048.., ld 3072), N=512, K=1024. grid (2, 8).
// ======================================================================
__global__ void __launch_bounds__(512) fp16_atth_kernel(
    const float* __restrict__ b_h2a)
{
    constexpr int ASZ = 128 * 128;
    constexpr int BSZ = 256 * 128;
    constexpr int STG = ASZ + BSZ;
    constexpr int T = 16;

    const __half* Ah = g_A1 + 2048;          // h1 fp16 (ld 3072)
    const __half* Wh = g_Wh2a_h;             // ld 1024

    extern __shared__ char smc[];
    const uint32_t smu = smem_u32(smc);

    const int tid = threadIdx.x;
    const int lane = tid & 31, w = tid >> 5;
    const int wm = w & 3, wn = w >> 2;
    const int g = lane >> 2, tig = lane & 3;
    const int sub = lane >> 3, sr = lane & 7;
    const int m0 = blockIdx.y * 128, n0 = blockIdx.x * 256;

    float acc[2][8][4];
#pragma unroll
    for (int mt = 0; mt < 2; mt++)
#pragma unroll
        for (int nt = 0; nt < 8; nt++)
#pragma unroll
            for (int r = 0; r < 4; r++) acc[mt][nt][r] = 0.f;

    auto prefetch = [&](int t, int buf) {
        const int kk = t * 64;
        const uint32_t abase = smu + (uint32_t)buf * STG;
        const uint32_t bbase = abase + ASZ;
#pragma unroll
        for (int i = 0; i < 2; i++) {
            int q = tid + i * 512;
            int row = q >> 3, c = q & 7;
            CP_ASYNC16(abase + row * 128 + ((c ^ (row & 7)) << 4),
                       (const void*)&Ah[(size_t)(m0 + row) * 3072 + kk + c * 8]);
        }
#pragma unroll
        for (int i = 0; i < 4; i++) {
            int q = tid + i * 512;
            int row = q >> 3, c = q & 7;
            CP_ASYNC16(bbase + row * 128 + ((c ^ (row & 7)) << 4),
                       (const void*)&Wh[(size_t)(n0 + row) * 1024 + kk + c * 8]);
        }
        CP_COMMIT();
    };

    prefetch(0, 0);
    prefetch(1, 1);

    for (int t = 0; t < T; t++) {
        const int buf = t % 3;
        if (t + 2 < T) { prefetch(t + 2, (t + 2) % 3); CP_WAIT2(); }
        else if (t + 1 < T) { CP_WAIT1(); }
        else { CP_WAIT0(); }
        __syncthreads();

        const uint32_t abase = smu + (uint32_t)buf * STG;
        const uint32_t bbase = abase + ASZ;

#pragma unroll
        for (int s = 0; s < 4; s++) {
            uint32_t a[2][4];
#pragma unroll
            for (int mt = 0; mt < 2; mt++) {
                int r = wm * 32 + mt * 16 + (sub & 1) * 8 + sr;
                int ch = 2 * s + (sub >> 1);
                LDMX4(a[mt][0], a[mt][1], a[mt][2], a[mt][3],
                      abase + r * 128 + ((ch ^ (r & 7)) << 4));
            }
#pragma unroll
            for (int ntp = 0; ntp < 4; ntp++) {
                int r = wn * 64 + ntp * 16 + ((sub >> 1) & 1) * 8 + sr;
                int ch = 2 * s + (sub & 1);
                uint32_t b0, b1, b2, b3;
                LDMX4(b0, b1, b2, b3, bbase + r * 128 + ((ch ^ (r & 7)) << 4));
                mma_f16(acc[0][2 * ntp],     a[0], b0, b1);
                mma_f16(acc[1][2 * ntp],     a[1], b0, b1);
                mma_f16(acc[0][2 * ntp + 1], a[0], b2, b3);
                mma_f16(acc[1][2 * ntp + 1], a[1], b2, b3);
            }
        }
        __syncthreads();
    }

#pragma unroll
    for (int mt = 0; mt < 2; mt++) {
        const int r0 = m0 + wm * 32 + mt * 16 + g;
        const int r1 = r0 + 8;
#pragma unroll
        for (int nt = 0; nt < 8; nt++) {
            const int cb = n0 + wn * 64 + nt * 8 + tig * 2;
            float2 bA = *(const float2*)&b_h2a[cb];
            const float* a = acc[mt][nt];
            float2 v0 = { a[0] + bA.x, a[1] + bA.y };
            float2 v1 = { a[2] + bA.x, a[3] + bA.y };
            *(float2*)&g_atth[(size_t)r0 * 512 + cb] = v0;
            *(float2*)&g_atth[(size_t)r1 * 512 + cb] = v1;
        }
    }
}

// ======================================================================
// scores GEMM with in-kernel fp32->fp16 conversion of clip:
// scores[row] += sum_n Walpha[n]*tanh(clip@Wctx^T + bctx + atth[b]) (atomic)
// M=65536, N=512, K=1024; BM=128 (2 batches), BN=256; grid (2, 512).
// smem: AH 2x16384 | WB 2x32768 | STAGE 2x32768 = 163840 B.
// Loop = validated R16 3-barrier pattern (reuse / copy-visible / tile-ready).
// ======================================================================
__global__ void __launch_bounds__(512) fp16_scores_kernel(
    const float* __restrict__ clip,
    const float* __restrict__ e0, const float* __restrict__ e1)
{
    constexpr int T = 16;
    extern __shared__ char smc[];
    const uint32_t smu = smem_u32(smc);
    const uint32_t AH    = smu;               // 2 x 16384
    const uint32_t WB    = smu + 32768;       // 2 x 32768
    const uint32_t STAGE = smu + 98304;       // 2 x 32768 (fp32 clip stage)

    const int tid = threadIdx.x;
    const int lane = tid & 31, w = tid >> 5;
    const int wm = w & 3, wn = w >> 2;
    const int g = lane >> 2, tig = lane & 3;
    const int sub = lane >> 3, sr = lane & 7;
    const int m0 = blockIdx.y * 128, n0 = blockIdx.x * 256;

    float acc[2][8][4];
#pragma unroll
    for (int mt = 0; mt < 2; mt++)
#pragma unroll
        for (int nt = 0; nt < 8; nt++)
#pragma unroll
            for (int r = 0; r < 4; r++) acc[mt][nt][r] = 0.f;

    auto issue = [&](int t) {
        const int buf = t & 1;
        const int kk = t * 64;
        const uint32_t wb = WB + (uint32_t)buf * 32768;
        const uint32_t st = STAGE + (uint32_t)buf * 32768;
#pragma unroll
        for (int i = 0; i < 4; i++) {            // W: 2048 x 16B
            int q = tid + i * 512;
            int row = q >> 3, c = q & 7;
            CP_ASYNC16(wb + row * 128 + ((c ^ (row & 7)) << 4),
                       (const void*)&g_Wctx_h[(size_t)(n0 + row) * 1024 + kk + c * 8]);
        }
#pragma unroll
        for (int i = 0; i < 4; i++) {            // clip fp32: 2048 x 16B
            int q = tid + i * 512;
            int row = q >> 4, c4 = q & 15;
            CP_ASYNC16(st + row * 256 + c4 * 16,
                       (const void*)&clip[(size_t)(m0 + row) * 1024 + kk + c4 * 4]);
        }
        CP_COMMIT();
    };

    issue(0);

    for (int t = 0; t < T; t++) {
        const int buf = t & 1;
        __syncthreads();                          // prev consumers done (buf reuse)
        if (t + 1 < T) { issue(t + 1); CP_WAIT1(); }
        else { CP_WAIT0(); }
        __syncthreads();                          // group-t copies visible to all
        {
            // convert stage -> AH[buf]: 1024 chunks of 16B fp16, 2 per thread
            const char* st = smc + 98304 + buf * 32768;
            const uint32_t ah = AH + (uint32_t)buf * 16384;
#pragma unroll
            for (int i = 0; i < 2; i++) {
                int q = tid + i * 512;
                int row = q >> 3, cc = q & 7;
                float4 v0 = *(const float4*)(st + row * 256 + cc * 32);
                float4 v1 = *(const float4*)(st + row * 256 + cc * 32 + 16);
                __half h[8] = { __float2half(v0.x), __float2half(v0.y),
                                __float2half(v0.z), __float2half(v0.w),
                                __float2half(v1.x), __float2half(v1.y),
                                __float2half(v1.z), __float2half(v1.w) };
                *(uint4*)(smc + (AH - smu) + buf * 16384 + row * 128 +
                          ((cc ^ (row & 7)) << 4)) = *(uint4*)h;
                (void)ah;
            }
        }
        __syncthreads();                          // AH tile ready

        const uint32_t abase = AH + (uint32_t)buf * 16384;
        const uint32_t bbase = WB + (uint32_t)buf * 32768;
#pragma unroll
        for (int s = 0; s < 4; s++) {
            uint32_t a[2][4];
#pragma unroll
            for (int mt = 0; mt < 2; mt++) {
                int r = wm * 32 + mt * 16 + (sub & 1) * 8 + sr;
                int ch = 2 * s + (sub >> 1);
                LDMX4(a[mt][0], a[mt][1], a[mt][2], a[mt][3],
                      abase + r * 128 + ((ch ^ (r & 7)) << 4));
            }
#pragma unroll
            for (int ntp = 0; ntp < 4; ntp++) {
                int r = wn * 64 + ntp * 16 + ((sub >> 1) & 1) * 8 + sr;
                int ch = 2 * s + (sub & 1);
                uint32_t b0, b1, b2, b3;
                LDMX4(b0, b1, b2, b3, bbase + r * 128 + ((ch ^ (r & 7)) << 4));
                mma_f16(acc[0][2 * ntp],     a[0], b0, b1);
                mma_f16(acc[1][2 * ntp],     a[1], b0, b1);
                mma_f16(acc[0][2 * ntp + 1], a[0], b2, b3);
                mma_f16(acc[1][2 * ntp + 1], a[1], b2, b3);
            }
        }
    }

    // scores epilogue (validated R14): tanh + W_alpha reduce + atomics
#pragma unroll
    for (int mt = 0; mt < 2; mt++) {
        const int r0 = m0 + wm * 32 + mt * 16 + g;
        const int r1 = r0 + 8;
        const int bb0 = r0 >> 6, bb1 = r1 >> 6;
        float s0 = 0.f, s1 = 0.f;
#pragma unroll
        for (int nt = 0; nt < 8; nt++) {
            const int cb = n0 + wn * 64 + nt * 8 + tig * 2;
            float2 bc = *(const float2*)&e0[cb];
            float2 wa = *(const float2*)&e1[cb];
            float2 a0 = *(const float2*)&g_atth[(size_t)bb0 * 512 + cb];
            float2 a1 = *(const float2*)&g_atth[(size_t)bb1 * 512 + cb];
            const float* a = acc[mt][nt];
            s0 += tanhf(a[0] + bc.x + a0.x) * wa.x + tanhf(a[1] + bc.y + a0.y) * wa.y;
            s1 += tanhf(a[2] + bc.x + a1.x) * wa.x + tanhf(a[3] + bc.y + a1.y) * wa.y;
        }
        s0 += __shfl_xor_sync(0xffffffffu, s0, 1);
        s0 += __shfl_xor_sync(0xffffffffu, s0, 2);
        s1 += __shfl_xor_sync(0xffffffffu, s1, 1);
        s1 += __shfl_xor_sync(0xffffffffu, s1, 2);
        if (tig == 0) {
            atomicAdd(&g_scores[r0], s0);
            atomicAdd(&g_scores[r1], s1);
        }
    }
}

// ======================================================================
// context: masked softmax over S=64 + weighted sum of fp32 clip,
// writes fp16 att directly into g_A1 cols 1024..2047 (validated R12 logic)
// ======================================================================
__global__ __launch_bounds__(256) void context_kernel(
    const float* __restrict__ clip, const int* __restrict__ mask)
{
    const int b = blockIdx.x;
    const int tid = threadIdx.x;
    __shared__ float ww[64];
    __shared__ float stat;

    if (tid < 64) ww[tid] = g_scores[b * 64 + tid];
    __syncthreads();
    if (tid == 0) {
        float m = ww[0];
        for (int s = 1; s < 64; s++) m = fmaxf(m, ww[s]);
        stat = m;
    }
    __syncthreads();
    if (tid < 64) ww[tid] = expf(ww[tid] - stat) * (float)mask[b * 64 + tid];
    __syncthreads();
    if (tid == 0) {
        float s = 0.f;
        for (int i = 0; i < 64; i++) s += ww[i];
        stat = s;
    }
    __syncthreads();
    if (tid < 64) ww[tid] = ww[tid] / stat;
    __syncthreads();

    for (int d = tid; d < 1024; d += 256) {
        float acc = 0.f;
#pragma unroll 8
        for (int s = 0; s < 64; s++)
            acc += ww[s] * clip[((size_t)b * 64 + s) * 1024 + d];
        g_A1[(size_t)b * 3072 + 1024 + d] = __float2half(acc);
    }
}

// ======================================================================
// LSTM pointwise
// ======================================================================
__global__ __launch_bounds__(256) void lstm_pointwise_kernel(
    const float* __restrict__ state_c, int stream, float* __restrict__ out)
{
    int idx = blockIdx.x * blockDim.x + threadIdx.x;
    int b = idx >> 10, j = idx & 1023;
    const float* g = g_gates + (size_t)b * 4096;
    float ig = 1.f / (1.f + expf(-g[j]));
    float fg = 1.f / (1.f + expf(-g[1024 + j]));
    float gg = tanhf(g[2048 + j]);
    float og = 1.f / (1.f + expf(-g[3072 + j]));
    float c_old = state_c[(size_t)stream * 1048576 + idx];
    float c_new = fg * c_old + ig * gg;
    float h_new = og * tanhf(c_new);
    out[(size_t)b * 2048 + stream * 1024 + j] = h_new;
    out[2097152 + (size_t)stream * 1048576 + idx] = h_new;
    out[4194304 + (size_t)stream * 1048576 + idx] = c_new;
}

// ======================================================================
extern "C" void kernel_launch(void* const* d_in, const int* in_sizes, int n_in,
                              void* d_out, int out_size)
{
    const float* xt       = (const float*)d_in[0];
    const float* event    = (const float*)d_in[2];
    const float* clip     = (const float*)d_in[3];
    const int*   clipmask = (const int*)  d_in[4];
    const float* state_h  = (const float*)d_in[5];
    const float* state_c  = (const float*)d_in[6];
    const float* W_ih0    = (const float*)d_in[7];
    const float* b_ih0    = (const float*)d_in[8];
    const float* W_hh0    = (const float*)d_in[9];
    const float* b_hh0    = (const float*)d_in[10];
    const float* W_ih1    = (const float*)d_in[11];
    const float* b_ih1    = (const float*)d_in[12];
    const float* W_hh1    = (const float*)d_in[13];
    const float* b_hh1    = (const float*)d_in[14];
    const float* W_ctx    = (const float*)d_in[15];
    const float* b_ctx    = (const float*)d_in[16];
    const float* W_h2a    = (const float*)d_in[17];
    const float* b_h2a    = (const float*)d_in[18];
    const float* W_alpha  = (const float*)d_in[19];
    const float* b_alpha  = (const float*)d_in[20];
    float* out = (float*)d_out;

    const float* h0 = state_h;
    const float* h1 = state_h + 1048576;

    const int SMEM_G = 3 * 49152;   // 147456 B (gates/atth, 3-stage fp16)
    const int SMEM_S = 163840;      // scores (AH 32K + WB 64K + STAGE 64K)
    cudaFuncSetAttribute(fp16_gates_kernel,
                         cudaFuncAttributeMaxDynamicSharedMemorySize, SMEM_G);
    cudaFuncSetAttribute(fp16_atth_kernel,
                         cudaFuncAttributeMaxDynamicSharedMemorySize, SMEM_G);
    cudaFuncSetAttribute(fp16_scores_kernel,
                         cudaFuncAttributeMaxDynamicSharedMemorySize, SMEM_S);

    // ---- operand conversions (fp32 -> fp16) ----
    conv_w512_kernel<<<512, 256>>>(W_ctx, 0);
    conv_w512_kernel<<<512, 256>>>(W_h2a, 1);
    conv_w_kernel<<<(4096 * 768 + 255) / 256, 256>>>(W_ih0, W_hh0, 0);
    conv_w_kernel<<<(4096 * 768 + 255) / 256, 256>>>(W_ih1, W_hh1, 1);
    conv_a_kernel<<<1024, 256>>>(xt,    0, 0);
    conv_a_kernel<<<1024, 256>>>(event, 0, 1024);
    conv_a_kernel<<<1024, 256>>>(h0,    0, 2048);
    conv_a_kernel<<<1024, 256>>>(xt,    1, 0);
    conv_a_kernel<<<1024, 256>>>(h1,    1, 2048);
    init_scores_kernel<<<256, 256>>>(b_alpha);

    // ---- attention pre-work: atth = h1_fp16 @ Wh2a^T + b_h2a ----
    fp16_atth_kernel<<<dim3(2, 8), 512, SMEM_G>>>(b_h2a);

    // ---- stream 0 LSTM ----
    fp16_gates_kernel<<<dim3(16, 8), 512, SMEM_G>>>(0, b_ih0, b_hh0);
    lstm_pointwise_kernel<<<4096, 256>>>(state_c, 0, out);

    // ---- attention: scores (in-kernel clip conversion) + context ----
    fp16_scores_kernel<<<dim3(2, 512), 512, SMEM_S>>>(clip, b_ctx, W_alpha);
    context_kernel<<<1024, 256>>>(clip, clipmask);

    // ---- stream 1 LSTM ----
    fp16_gates_kernel<<<dim3(16, 8), 512, SMEM_G>>>(1, b_ih1, b_hh1);
    lstm_pointwise_kernel<<<4096, 256>>>(state_c, 1, out);
}